// round 1
// baseline (speedup 1.0000x reference)
#include <cuda_runtime.h>
#include <math.h>

// ---------------- problem shapes ----------------
// B=2, S=4096, D=2048, H=16, DK=DV=128, SEG=512, NSEG=8, DH=8192, M=B*S=8192

// ---------------- scratch (static device globals; allocation-free) ----------------
static __device__ float g_Q[8192 * 2048];
static __device__ float g_K[8192 * 2048];
static __device__ float g_V[8192 * 2048];
static __device__ float g_attdot[8192 * 2048];
static __device__ float g_att[8192 * 2048];
static __device__ float g_P[2 * 16 * 8 * 128 * 128];
static __device__ float g_Mpre[2 * 16 * 8 * 128 * 128];
static __device__ float g_zz[2 * 16 * 8 * 128];
static __device__ float g_zpre[2 * 16 * 8 * 128];
static __device__ float g_ao[8192 * 2048];
static __device__ float g_hb[67108864];         // 8192 * 8192
static __device__ float g_yb[8192 * 2048];

// ---------------- generic SGEMM: C[M,N] = A[M,K] @ B[K,N] (+bias)(+relu) ----------------
// BM=BN=128, BK=8, 256 threads, 8x8 microtile, double-buffered smem.
template <bool BIAS, bool RELU>
__global__ __launch_bounds__(256) void sgemm_k(
    const float* __restrict__ A, const float* __restrict__ B,
    const float* __restrict__ bias, float* __restrict__ C,
    int M, int N, int K)
{
    __shared__ float As[2][8][128];   // transposed: As[k][m]
    __shared__ float Bs[2][8][128];

    const int tid = threadIdx.x;
    const int ty = tid >> 4, tx = tid & 15;
    const int row0 = blockIdx.y * 128;
    const int col0 = blockIdx.x * 128;

    const int arow = tid >> 1;
    const int acol = (tid & 1) << 2;
    const int brow = tid >> 5;
    const int bcol = (tid & 31) << 2;

    const float* Ap = A + (size_t)(row0 + arow) * K + acol;
    const float* Bp = B + (size_t)brow * N + col0 + bcol;

    float4 ar = *(const float4*)Ap;
    float4 br = *(const float4*)Bp;
    As[0][acol + 0][arow] = ar.x;
    As[0][acol + 1][arow] = ar.y;
    As[0][acol + 2][arow] = ar.z;
    As[0][acol + 3][arow] = ar.w;
    *(float4*)&Bs[0][brow][bcol] = br;
    __syncthreads();

    float acc[8][8] = {};
    const int nt = K >> 3;
    int buf = 0;
    for (int t = 0; t < nt; ++t) {
        if (t + 1 < nt) {
            ar = *(const float4*)(Ap + (size_t)(t + 1) * 8);
            br = *(const float4*)(Bp + (size_t)(t + 1) * 8 * N);
        }
#pragma unroll
        for (int k = 0; k < 8; ++k) {
            float af[8], bf[8];
            *(float4*)&af[0] = *(const float4*)&As[buf][k][ty * 8];
            *(float4*)&af[4] = *(const float4*)&As[buf][k][ty * 8 + 4];
            *(float4*)&bf[0] = *(const float4*)&Bs[buf][k][tx * 8];
            *(float4*)&bf[4] = *(const float4*)&Bs[buf][k][tx * 8 + 4];
#pragma unroll
            for (int i = 0; i < 8; ++i)
#pragma unroll
                for (int j = 0; j < 8; ++j)
                    acc[i][j] += af[i] * bf[j];
        }
        if (t + 1 < nt) {
            buf ^= 1;
            As[buf][acol + 0][arow] = ar.x;
            As[buf][acol + 1][arow] = ar.y;
            As[buf][acol + 2][arow] = ar.z;
            As[buf][acol + 3][arow] = ar.w;
            *(float4*)&Bs[buf][brow][bcol] = br;
            __syncthreads();
        }
    }

#pragma unroll
    for (int i = 0; i < 8; ++i) {
        const int r = row0 + ty * 8 + i;
        float* Cp = C + (size_t)r * N + col0 + tx * 8;
#pragma unroll
        for (int j = 0; j < 8; ++j) {
            float v = acc[i][j];
            if (BIAS) v += bias[col0 + tx * 8 + j];
            if (RELU) v = fmaxf(v, 0.f);
            Cp[j] = v;
        }
    }
}

// ---------------- intra-segment causal flash attention (fp32) ----------------
// grid (qtile=8, seg=8, b*h=32), 256 threads. 64-row Q tile, 64-row KV tiles.
__global__ __launch_bounds__(256) void attdot_k(
    const float* __restrict__ Q, const float* __restrict__ Kg,
    const float* __restrict__ Vg, float* __restrict__ Od)
{
    extern __shared__ float sm[];
    float* QsT = sm;                 // [128][64]
    float* KsT = QsT + 128 * 64;     // [128][64]
    float* Vs  = KsT + 128 * 64;     // [64][128]
    float* PsT = Vs + 64 * 128;      // [64][68]  (padded stride 68)

    const int tid = threadIdx.x;
    const int ty = tid >> 4, tx = tid & 15;
    const int bh = blockIdx.z;
    const int b = bh >> 4, h = bh & 15;
    const int seg = blockIdx.y, qt = blockIdx.x;
    const int rowbase = b * 4096 + seg * 512;
    const float scale = 0.08838834764831845f;   // 1/sqrt(128)

#pragma unroll
    for (int u = 0; u < 8; ++u) {
        int fi = tid + u * 256;
        int r = fi >> 5;
        int c = (fi & 31) << 2;
        float4 v = *(const float4*)&Q[(size_t)(rowbase + qt * 64 + r) * 2048 + h * 128 + c];
        QsT[(c + 0) * 64 + r] = v.x * scale;
        QsT[(c + 1) * 64 + r] = v.y * scale;
        QsT[(c + 2) * 64 + r] = v.z * scale;
        QsT[(c + 3) * 64 + r] = v.w * scale;
    }

    float Oa[4][8] = {};
    float mrow[4] = {-INFINITY, -INFINITY, -INFINITY, -INFINITY};
    float lrow[4] = {};

    const int r0 = ty * 4, c0 = tx * 4, oc0 = tx * 8;

    for (int j = 0; j <= qt; ++j) {
        __syncthreads();   // protect KsT/Vs/PsT reuse
#pragma unroll
        for (int u = 0; u < 8; ++u) {
            int fi = tid + u * 256;
            int r = fi >> 5;
            int c = (fi & 31) << 2;
            size_t gi = (size_t)(rowbase + j * 64 + r) * 2048 + h * 128 + c;
            float4 kv = *(const float4*)&Kg[gi];
            KsT[(c + 0) * 64 + r] = kv.x;
            KsT[(c + 1) * 64 + r] = kv.y;
            KsT[(c + 2) * 64 + r] = kv.z;
            KsT[(c + 3) * 64 + r] = kv.w;
            *(float4*)&Vs[r * 128 + c] = *(const float4*)&Vg[gi];
        }
        __syncthreads();

        float s[4][4] = {};
#pragma unroll 4
        for (int k = 0; k < 128; ++k) {
            float4 a4 = *(const float4*)&QsT[k * 64 + r0];
            float4 b4 = *(const float4*)&KsT[k * 64 + c0];
            float av[4] = {a4.x, a4.y, a4.z, a4.w};
            float bv[4] = {b4.x, b4.y, b4.z, b4.w};
#pragma unroll
            for (int i = 0; i < 4; ++i)
#pragma unroll
                for (int jj = 0; jj < 4; ++jj)
                    s[i][jj] += av[i] * bv[jj];
        }

        if (j == qt) {
#pragma unroll
            for (int i = 0; i < 4; ++i)
#pragma unroll
                for (int jj = 0; jj < 4; ++jj)
                    if (c0 + jj > r0 + i) s[i][jj] = -INFINITY;
        }

#pragma unroll
        for (int i = 0; i < 4; ++i) {
            float rm = fmaxf(fmaxf(s[i][0], s[i][1]), fmaxf(s[i][2], s[i][3]));
#pragma unroll
            for (int off = 8; off >= 1; off >>= 1)
                rm = fmaxf(rm, __shfl_xor_sync(0xffffffffu, rm, off, 16));
            float mn = fmaxf(mrow[i], rm);
            float sc = expf(mrow[i] - mn);     // first iter: exp(-inf)=0
            mrow[i] = mn;
            float rs = 0.f;
#pragma unroll
            for (int jj = 0; jj < 4; ++jj) {
                float e = expf(s[i][jj] - mn);
                rs += e;
                PsT[(c0 + jj) * 68 + r0 + i] = e;
            }
#pragma unroll
            for (int off = 8; off >= 1; off >>= 1)
                rs += __shfl_xor_sync(0xffffffffu, rs, off, 16);
            lrow[i] = lrow[i] * sc + rs;
#pragma unroll
            for (int c = 0; c < 8; ++c) Oa[i][c] *= sc;
        }
        __syncthreads();

#pragma unroll 2
        for (int kv = 0; kv < 64; ++kv) {
            float4 a4 = *(const float4*)&PsT[kv * 68 + r0];
            float av[4] = {a4.x, a4.y, a4.z, a4.w};
            float4 b0 = *(const float4*)&Vs[kv * 128 + oc0];
            float4 b1 = *(const float4*)&Vs[kv * 128 + oc0 + 4];
            float bv[8] = {b0.x, b0.y, b0.z, b0.w, b1.x, b1.y, b1.z, b1.w};
#pragma unroll
            for (int i = 0; i < 4; ++i)
#pragma unroll
                for (int c = 0; c < 8; ++c)
                    Oa[i][c] += av[i] * bv[c];
        }
    }

#pragma unroll
    for (int i = 0; i < 4; ++i) {
        float inv = 1.f / lrow[i];
        size_t base = (size_t)(rowbase + qt * 64 + r0 + i) * 2048 + h * 128 + oc0;
#pragma unroll
        for (int c = 0; c < 8; ++c)
            Od[base + c] = Oa[i][c] * inv;
    }
}

// ---------------- per-segment memory outer product P = sig_kT @ v (128x128, K=512) ----------------
__global__ __launch_bounds__(256) void pmat_k(
    const float* __restrict__ Kg, const float* __restrict__ Vg, float* __restrict__ P)
{
    __shared__ float sk[16][128];
    __shared__ float sv[16][128];
    const int tid = threadIdx.x;
    const int ty = tid >> 4, tx = tid & 15;
    const int seg = blockIdx.x, bh = blockIdx.y;
    const int b = bh >> 4, h = bh & 15;
    const int rowbase = b * 4096 + seg * 512;
    float acc[8][8] = {};

    for (int ck = 0; ck < 512; ck += 16) {
        __syncthreads();
#pragma unroll
        for (int u = 0; u < 2; ++u) {
            int fi = tid + u * 256;
            int r = fi >> 5;
            int c = (fi & 31) << 2;
            size_t gi = (size_t)(rowbase + ck + r) * 2048 + h * 128 + c;
            float4 kv = *(const float4*)&Kg[gi];
            float4 e;
            e.x = kv.x > 0.f ? kv.x + 1.f : expf(kv.x);
            e.y = kv.y > 0.f ? kv.y + 1.f : expf(kv.y);
            e.z = kv.z > 0.f ? kv.z + 1.f : expf(kv.z);
            e.w = kv.w > 0.f ? kv.w + 1.f : expf(kv.w);
            *(float4*)&sk[r][c] = e;
            *(float4*)&sv[r][c] = *(const float4*)&Vg[gi];
        }
        __syncthreads();
#pragma unroll
        for (int s = 0; s < 16; ++s) {
            float av[8], bv[8];
            *(float4*)&av[0] = *(const float4*)&sk[s][ty * 8];
            *(float4*)&av[4] = *(const float4*)&sk[s][ty * 8 + 4];
            *(float4*)&bv[0] = *(const float4*)&sv[s][tx * 8];
            *(float4*)&bv[4] = *(const float4*)&sv[s][tx * 8 + 4];
#pragma unroll
            for (int i = 0; i < 8; ++i)
#pragma unroll
                for (int j = 0; j < 8; ++j)
                    acc[i][j] += av[i] * bv[j];
        }
    }

    float* Pp = P + ((size_t)bh * 8 + seg) * 16384;
#pragma unroll
    for (int i = 0; i < 8; ++i)
#pragma unroll
        for (int j = 0; j < 8; ++j)
            Pp[(ty * 8 + i) * 128 + tx * 8 + j] = acc[i][j];
}

// ---------------- z_i = sum_s elu(k)+1 over the segment ----------------
__global__ void zsum_k(const float* __restrict__ Kg, float* __restrict__ z)
{
    int d = threadIdx.x;            // 128
    int seg = blockIdx.x, bh = blockIdx.y;
    int b = bh >> 4, h = bh & 15;
    const float* Kp = Kg + (size_t)(b * 4096 + seg * 512) * 2048 + h * 128 + d;
    float s = 0.f;
    for (int i = 0; i < 512; ++i) {
        float x = Kp[(size_t)i * 2048];
        s += x > 0.f ? x + 1.f : expf(x);
    }
    z[((size_t)bh * 8 + seg) * 128 + d] = s;
}

// ---------------- exclusive prefix over segments (mem and z carries) ----------------
__global__ void prefix_k(const float* __restrict__ P, const float* __restrict__ z,
                         float* __restrict__ Mpre, float* __restrict__ zpre)
{
    int bh = blockIdx.x;
    int tid = threadIdx.x;          // 256
    for (int idx = tid; idx < 16384; idx += 256) {
        float run = 0.f;
        for (int s = 0; s < 8; ++s) {
            size_t o = ((size_t)bh * 8 + s) * 16384 + idx;
            Mpre[o] = run;
            run += P[o];
        }
    }
    if (tid < 128) {
        float run = 1.f / 128.f;
        for (int s = 0; s < 8; ++s) {
            size_t o = ((size_t)bh * 8 + s) * 128 + tid;
            zpre[o] = run;
            run += z[o];
        }
    }
}

// ---------------- att_mem + gated blend with att_dot ----------------
// grid (qtile=8, seg=8, b*h=32), 256 threads.
__global__ __launch_bounds__(256) void combine_k(
    const float* __restrict__ Q, const float* __restrict__ Mpre,
    const float* __restrict__ zpre, const float* __restrict__ attdot,
    const float* __restrict__ betas, float* __restrict__ att)
{
    extern __shared__ float sm[];
    float* sqT = sm;                  // [128][64]
    float* Ms  = sqT + 128 * 64;      // [128][128]
    float* zs  = Ms + 128 * 128;      // [128]

    const int tid = threadIdx.x;
    const int ty = tid >> 4, tx = tid & 15;
    const int bh = blockIdx.z, b = bh >> 4, h = bh & 15;
    const int seg = blockIdx.y, qt = blockIdx.x;
    const int rowbase = b * 4096 + seg * 512;

#pragma unroll
    for (int u = 0; u < 8; ++u) {
        int fi = tid + u * 256;
        int r = fi >> 5;
        int c = (fi & 31) << 2;
        float4 v = *(const float4*)&Q[(size_t)(rowbase + qt * 64 + r) * 2048 + h * 128 + c];
        sqT[(c + 0) * 64 + r] = v.x > 0.f ? v.x + 1.f : expf(v.x);
        sqT[(c + 1) * 64 + r] = v.y > 0.f ? v.y + 1.f : expf(v.y);
        sqT[(c + 2) * 64 + r] = v.z > 0.f ? v.z + 1.f : expf(v.z);
        sqT[(c + 3) * 64 + r] = v.w > 0.f ? v.w + 1.f : expf(v.w);
    }
    {
        const float4* Mg = (const float4*)(Mpre + ((size_t)bh * 8 + seg) * 16384);
        float4* Ms4 = (float4*)Ms;
        for (int i = tid; i < 4096; i += 256) Ms4[i] = Mg[i];
        if (tid < 128) zs[tid] = zpre[((size_t)bh * 8 + seg) * 128 + tid];
    }
    __syncthreads();

    const int r0 = ty * 4, oc0 = tx * 8;
    float acc[4][8] = {};
    float den[4] = {};
#pragma unroll 4
    for (int k = 0; k < 128; ++k) {
        float4 a4 = *(const float4*)&sqT[k * 64 + r0];
        float av[4] = {a4.x, a4.y, a4.z, a4.w};
        float zk = zs[k];
        float4 b0 = *(const float4*)&Ms[k * 128 + oc0];
        float4 b1 = *(const float4*)&Ms[k * 128 + oc0 + 4];
        float bv[8] = {b0.x, b0.y, b0.z, b0.w, b1.x, b1.y, b1.z, b1.w};
#pragma unroll
        for (int i = 0; i < 4; ++i) {
            den[i] += av[i] * zk;
#pragma unroll
            for (int c = 0; c < 8; ++c)
                acc[i][c] += av[i] * bv[c];
        }
    }

#pragma unroll
    for (int i = 0; i < 4; ++i) {
        float inv = 1.f / den[i];
        size_t base = (size_t)(rowbase + qt * 64 + r0 + i) * 2048 + h * 128 + oc0;
#pragma unroll
        for (int c = 0; c < 8; ++c) {
            float g = 1.f / (1.f + expf(-betas[h * 128 + oc0 + c]));
            float am = acc[i][c] * inv;
            float ad = attdot[base + c];
            att[base + c] = g * am + (1.f - g) * ad;
        }
    }
}

// ---------------- residual + LayerNorm ----------------
__global__ __launch_bounds__(256) void ln_k(
    const float* __restrict__ y, const float* __restrict__ x,
    const float* __restrict__ gm, const float* __restrict__ bt,
    float* __restrict__ out)
{
    __shared__ float r1[8], r2[8];
    const int row = blockIdx.x, tid = threadIdx.x;
    const float* yp = y + (size_t)row * 2048;
    const float* xp = x + (size_t)row * 2048;
    float s1 = 0.f, s2 = 0.f;
    for (int c = tid; c < 2048; c += 256) {
        float v = yp[c] + xp[c];
        s1 += v; s2 += v * v;
    }
#pragma unroll
    for (int off = 16; off >= 1; off >>= 1) {
        s1 += __shfl_xor_sync(0xffffffffu, s1, off);
        s2 += __shfl_xor_sync(0xffffffffu, s2, off);
    }
    if ((tid & 31) == 0) { r1[tid >> 5] = s1; r2[tid >> 5] = s2; }
    __syncthreads();
    if (tid == 0) {
        float a = 0.f, bb = 0.f;
        for (int w = 0; w < 8; ++w) { a += r1[w]; bb += r2[w]; }
        r1[0] = a; r2[0] = bb;
    }
    __syncthreads();
    const float mu = r1[0] * (1.f / 2048.f);
    const float var = r2[0] * (1.f / 2048.f) - mu * mu;
    const float rs = rsqrtf(var + 1e-5f);
    for (int c = tid; c < 2048; c += 256) {
        float v = yp[c] + xp[c];
        out[(size_t)row * 2048 + c] = (v - mu) * rs * gm[c] + bt[c];
    }
}

// ---------------- host launcher ----------------
extern "C" void kernel_launch(void* const* d_in, const int* in_sizes, int n_in,
                              void* d_out, int out_size)
{
    const float* x     = (const float*)d_in[0];
    const float* Wq    = (const float*)d_in[1];
    const float* Wk    = (const float*)d_in[2];
    const float* Wv    = (const float*)d_in[3];
    const float* Wo    = (const float*)d_in[4];
    const float* betas = (const float*)d_in[5];
    const float* W1    = (const float*)d_in[6];
    const float* b1    = (const float*)d_in[7];
    const float* W2    = (const float*)d_in[8];
    const float* b2    = (const float*)d_in[9];
    const float* lng   = (const float*)d_in[10];
    const float* lnb   = (const float*)d_in[11];
    float* out = (float*)d_out;

    float *Qb, *Kb, *Vb, *AD, *AT, *Pb, *Mp, *zb, *zp, *AO, *HB, *YB;
    cudaGetSymbolAddress((void**)&Qb, g_Q);
    cudaGetSymbolAddress((void**)&Kb, g_K);
    cudaGetSymbolAddress((void**)&Vb, g_V);
    cudaGetSymbolAddress((void**)&AD, g_attdot);
    cudaGetSymbolAddress((void**)&AT, g_att);
    cudaGetSymbolAddress((void**)&Pb, g_P);
    cudaGetSymbolAddress((void**)&Mp, g_Mpre);
    cudaGetSymbolAddress((void**)&zb, g_zz);
    cudaGetSymbolAddress((void**)&zp, g_zpre);
    cudaGetSymbolAddress((void**)&AO, g_ao);
    cudaGetSymbolAddress((void**)&HB, g_hb);
    cudaGetSymbolAddress((void**)&YB, g_yb);

    const int ATT_SMEM = (128 * 64 + 128 * 64 + 64 * 128 + 64 * 68) * 4;   // 115712 B
    const int CMB_SMEM = (128 * 64 + 128 * 128 + 128) * 4;                 // 98816 B
    cudaFuncSetAttribute(attdot_k, cudaFuncAttributeMaxDynamicSharedMemorySize, ATT_SMEM);
    cudaFuncSetAttribute(combine_k, cudaFuncAttributeMaxDynamicSharedMemorySize, CMB_SMEM);

    dim3 g2048(2048 / 128, 8192 / 128);   // N=2048 GEMMs
    dim3 g8192(8192 / 128, 8192 / 128);   // N=8192 GEMM

    // QKV projections
    sgemm_k<false, false><<<g2048, 256>>>(x, Wq, nullptr, Qb, 8192, 2048, 2048);
    sgemm_k<false, false><<<g2048, 256>>>(x, Wk, nullptr, Kb, 8192, 2048, 2048);
    sgemm_k<false, false><<<g2048, 256>>>(x, Wv, nullptr, Vb, 8192, 2048, 2048);

    // intra-segment causal softmax attention
    dim3 ga(8, 8, 32);
    attdot_k<<<ga, 256, ATT_SMEM>>>(Qb, Kb, Vb, AD);

    // linear memory path: per-segment outer products + carries
    dim3 gz(8, 32);
    zsum_k<<<gz, 128>>>(Kb, zb);
    pmat_k<<<gz, 256>>>(Kb, Vb, Pb);
    prefix_k<<<32, 256>>>(Pb, zb, Mp, zp);
    combine_k<<<ga, 256, CMB_SMEM>>>(Qb, Mp, zp, AD, betas, AT);

    // output projection + MLP
    sgemm_k<false, false><<<g2048, 256>>>(AT, Wo, nullptr, AO, 8192, 2048, 2048);
    sgemm_k<true, true><<<g8192, 256>>>(AO, W1, b1, HB, 8192, 8192, 2048);
    sgemm_k<true, false><<<g2048, 256>>>(HB, W2, b2, YB, 8192, 2048, 8192);

    // residual + LayerNorm
    ln_k<<<8192, 256>>>(YB, x, lng, lnb, out);
}

// round 3
// speedup vs baseline: 2.6894x; 2.6894x over previous
#include <cuda_runtime.h>
#include <math.h>
#include <stdint.h>

// ---------------- shapes ----------------
// B=2, S=4096, D=2048, H=16, DK=DV=128, SEG=512, NSEG=8, DH=8192, M=B*S=8192
// QKV fused: stride 6144 (Q at col 0, K at 2048, V at 4096)

// ---------------- scratch ----------------
static __device__ float g_qkv[8192 * 6144];
static __device__ float g_attdot[8192 * 2048];
static __device__ float g_att[8192 * 2048];
static __device__ float g_P[2 * 16 * 8 * 128 * 128];
static __device__ float g_Mpre[2 * 16 * 8 * 128 * 128];
static __device__ float g_zz[2 * 16 * 8 * 128];
static __device__ float g_zpre[2 * 16 * 8 * 128];
static __device__ float g_ao[8192 * 2048];
static __device__ float g_hb[8192 * 8192];
static __device__ float g_yb[8192 * 2048];
static __device__ float g_WqkvT[6144 * 2048];
static __device__ float g_WoT[2048 * 2048];
static __device__ float g_W1T[8192 * 2048];
static __device__ float g_W2T[2048 * 8192];

// ---------------- helpers ----------------
__device__ __forceinline__ uint32_t smem_u32(const void* p) {
    uint32_t a;
    asm("{ .reg .u64 t; cvta.to.shared.u64 t, %1; cvt.u32.u64 %0, t; }" : "=r"(a) : "l"(p));
    return a;
}
__device__ __forceinline__ void cp16(uint32_t dst, const void* src) {
    asm volatile("cp.async.cg.shared.global [%0], [%1], 16;" :: "r"(dst), "l"(src) : "memory");
}
__device__ __forceinline__ uint32_t f2tf32(float v) {
    uint32_t o;
    asm("cvt.rna.tf32.f32 %0, %1;" : "=r"(o) : "f"(v));
    return o;
}
__device__ __forceinline__ void mma_tf32(float* c, const uint32_t* a, const uint32_t* b) {
    asm volatile("mma.sync.aligned.m16n8k8.row.col.f32.tf32.tf32.f32 "
        "{%0,%1,%2,%3}, {%4,%5,%6,%7}, {%8,%9}, {%0,%1,%2,%3};"
        : "+f"(c[0]), "+f"(c[1]), "+f"(c[2]), "+f"(c[3])
        : "r"(a[0]), "r"(a[1]), "r"(a[2]), "r"(a[3]), "r"(b[0]), "r"(b[1]));
}

// ---------------- tf32 tensor-core GEMM: C[M,N] = A[M,K] @ Bt[N,K]^T ----------------
// CTA tile 128x128, BK=16, 256 threads, 3-stage cp.async pipeline.
// smem row stride 20 floats -> conflict-free scalar fragment loads.
#define GSTAGE_F 5120                    // floats per stage (As 2560 + Bs 2560)
#define GEMM_SMEM (3 * GSTAGE_F * 4)     // 61440 bytes

template <bool BIAS, bool RELU>
__global__ __launch_bounds__(256, 2) void gemm_mma(
    const float* __restrict__ A, const float* __restrict__ Bt,
    const float* __restrict__ bias, float* __restrict__ C,
    int Nn, int K)
{
    extern __shared__ float sm[];
    const int tid = threadIdx.x;
    const int wid = tid >> 5, lane = tid & 31;
    const int group = lane >> 2, tig = lane & 3;
    const int wm = wid >> 2, wn = wid & 3;
    const int m0 = blockIdx.y * 128, n0 = blockIdx.x * 128;
    const int nt = K >> 4;

    const int lrow = tid >> 2;            // 0..63  (row pair index for loads)
    const int lkc  = (tid & 3) << 2;      // 0,4,8,12

    // ---- preload stages 0,1 ----
#pragma unroll
    for (int t = 0; t < 2; ++t) {
        float* As = sm + t * GSTAGE_F;
        float* Bs = As + 2560;
        const int k0 = t * 16;
#pragma unroll
        for (int j = 0; j < 2; ++j) {
            int row = lrow + j * 64;
            cp16(smem_u32(As + row * 20 + lkc), A + (size_t)(m0 + row) * K + k0 + lkc);
        }
#pragma unroll
        for (int j = 0; j < 2; ++j) {
            int row = lrow + j * 64;
            cp16(smem_u32(Bs + row * 20 + lkc), Bt + (size_t)(n0 + row) * K + k0 + lkc);
        }
        asm volatile("cp.async.commit_group;" ::: "memory");
    }

    float acc[4][4][4] = {};

    for (int t = 0; t < nt; ++t) {
        asm volatile("cp.async.wait_group 1;" ::: "memory");
        __syncthreads();

        if (t + 2 < nt) {
            const int s = (t + 2) % 3;
            float* As = sm + s * GSTAGE_F;
            float* Bs = As + 2560;
            const int k0 = (t + 2) * 16;
#pragma unroll
            for (int j = 0; j < 2; ++j) {
                int row = lrow + j * 64;
                cp16(smem_u32(As + row * 20 + lkc), A + (size_t)(m0 + row) * K + k0 + lkc);
            }
#pragma unroll
            for (int j = 0; j < 2; ++j) {
                int row = lrow + j * 64;
                cp16(smem_u32(Bs + row * 20 + lkc), Bt + (size_t)(n0 + row) * K + k0 + lkc);
            }
        }
        asm volatile("cp.async.commit_group;" ::: "memory");

        const float* As = sm + (t % 3) * GSTAGE_F;
        const float* Bs = As + 2560;

#pragma unroll
        for (int ks = 0; ks < 2; ++ks) {
            uint32_t af[4][4], bf[4][2];
            const int c = ks * 8 + tig;
#pragma unroll
            for (int mf = 0; mf < 4; ++mf) {
                const int r = wm * 64 + mf * 16 + group;
                af[mf][0] = f2tf32(As[r * 20 + c]);
                af[mf][1] = f2tf32(As[(r + 8) * 20 + c]);
                af[mf][2] = f2tf32(As[r * 20 + c + 4]);
                af[mf][3] = f2tf32(As[(r + 8) * 20 + c + 4]);
            }
#pragma unroll
            for (int nf = 0; nf < 4; ++nf) {
                const int n = wn * 32 + nf * 8 + group;
                bf[nf][0] = __float_as_uint(Bs[n * 20 + c]);
                bf[nf][1] = __float_as_uint(Bs[n * 20 + c + 4]);
            }
#pragma unroll
            for (int mf = 0; mf < 4; ++mf)
#pragma unroll
                for (int nf = 0; nf < 4; ++nf)
                    mma_tf32(acc[mf][nf], af[mf], bf[nf]);
        }
        __syncthreads();
    }

    // ---- epilogue: registers -> global ----
#pragma unroll
    for (int mf = 0; mf < 4; ++mf) {
        const int row = m0 + wm * 64 + mf * 16 + group;
#pragma unroll
        for (int nf = 0; nf < 4; ++nf) {
            const int col = n0 + wn * 32 + nf * 8 + 2 * tig;
            float2 v0 = make_float2(acc[mf][nf][0], acc[mf][nf][1]);
            float2 v1 = make_float2(acc[mf][nf][2], acc[mf][nf][3]);
            if (BIAS) {
                float b0 = bias[col], b1 = bias[col + 1];
                v0.x += b0; v0.y += b1; v1.x += b0; v1.y += b1;
            }
            if (RELU) {
                v0.x = fmaxf(v0.x, 0.f); v0.y = fmaxf(v0.y, 0.f);
                v1.x = fmaxf(v1.x, 0.f); v1.y = fmaxf(v1.y, 0.f);
            }
            *(float2*)&C[(size_t)row * Nn + col] = v0;
            *(float2*)&C[(size_t)(row + 8) * Nn + col] = v1;
        }
    }
}

// ---------------- weight transpose (+ RNA round to tf32) ----------------
__global__ __launch_bounds__(256) void transpose_k(
    const float* __restrict__ S, float* __restrict__ D, int R, int C)
{
    __shared__ float t[32][33];
    const int bx = blockIdx.x * 32, by = blockIdx.y * 32;
    const int lx = threadIdx.x & 31, ly = threadIdx.x >> 5;
#pragma unroll
    for (int i = 0; i < 32; i += 8) {
        float v = S[(size_t)(by + ly + i) * C + bx + lx];
        t[ly + i][lx] = __uint_as_float(f2tf32(v));
    }
    __syncthreads();
#pragma unroll
    for (int i = 0; i < 32; i += 8)
        D[(size_t)(bx + ly + i) * R + by + lx] = t[lx][ly + i];
}

// ---------------- intra-segment causal flash attention (fp32) ----------------
__global__ __launch_bounds__(256) void attdot_k(
    const float* __restrict__ Q, const float* __restrict__ Kg,
    const float* __restrict__ Vg, float* __restrict__ Od)
{
    extern __shared__ float sm[];
    float* QsT = sm;
    float* KsT = QsT + 128 * 64;
    float* Vs  = KsT + 128 * 64;
    float* PsT = Vs + 64 * 128;

    const int tid = threadIdx.x;
    const int ty = tid >> 4, tx = tid & 15;
    const int bh = blockIdx.z;
    const int b = bh >> 4, h = bh & 15;
    const int seg = blockIdx.y, qt = blockIdx.x;
    const int rowbase = b * 4096 + seg * 512;
    const float scale = 0.08838834764831845f;

#pragma unroll
    for (int u = 0; u < 8; ++u) {
        int fi = tid + u * 256;
        int r = fi >> 5;
        int c = (fi & 31) << 2;
        float4 v = *(const float4*)&Q[(size_t)(rowbase + qt * 64 + r) * 6144 + h * 128 + c];
        QsT[(c + 0) * 64 + r] = v.x * scale;
        QsT[(c + 1) * 64 + r] = v.y * scale;
        QsT[(c + 2) * 64 + r] = v.z * scale;
        QsT[(c + 3) * 64 + r] = v.w * scale;
    }

    float Oa[4][8] = {};
    float mrow[4] = {-INFINITY, -INFINITY, -INFINITY, -INFINITY};
    float lrow[4] = {};

    const int r0 = ty * 4, c0 = tx * 4, oc0 = tx * 8;

    for (int j = 0; j <= qt; ++j) {
        __syncthreads();
#pragma unroll
        for (int u = 0; u < 8; ++u) {
            int fi = tid + u * 256;
            int r = fi >> 5;
            int c = (fi & 31) << 2;
            size_t gi = (size_t)(rowbase + j * 64 + r) * 6144 + h * 128 + c;
            float4 kv = *(const float4*)&Kg[gi];
            KsT[(c + 0) * 64 + r] = kv.x;
            KsT[(c + 1) * 64 + r] = kv.y;
            KsT[(c + 2) * 64 + r] = kv.z;
            KsT[(c + 3) * 64 + r] = kv.w;
            *(float4*)&Vs[r * 128 + c] = *(const float4*)&Vg[gi];
        }
        __syncthreads();

        float s[4][4] = {};
#pragma unroll 4
        for (int k = 0; k < 128; ++k) {
            float4 a4 = *(const float4*)&QsT[k * 64 + r0];
            float4 b4 = *(const float4*)&KsT[k * 64 + c0];
            float av[4] = {a4.x, a4.y, a4.z, a4.w};
            float bv[4] = {b4.x, b4.y, b4.z, b4.w};
#pragma unroll
            for (int i = 0; i < 4; ++i)
#pragma unroll
                for (int jj = 0; jj < 4; ++jj)
                    s[i][jj] += av[i] * bv[jj];
        }

        if (j == qt) {
#pragma unroll
            for (int i = 0; i < 4; ++i)
#pragma unroll
                for (int jj = 0; jj < 4; ++jj)
                    if (c0 + jj > r0 + i) s[i][jj] = -INFINITY;
        }

#pragma unroll
        for (int i = 0; i < 4; ++i) {
            float rm = fmaxf(fmaxf(s[i][0], s[i][1]), fmaxf(s[i][2], s[i][3]));
#pragma unroll
            for (int off = 8; off >= 1; off >>= 1)
                rm = fmaxf(rm, __shfl_xor_sync(0xffffffffu, rm, off, 16));
            float mn = fmaxf(mrow[i], rm);
            float sc = expf(mrow[i] - mn);
            mrow[i] = mn;
            float rs = 0.f;
#pragma unroll
            for (int jj = 0; jj < 4; ++jj) {
                float e = expf(s[i][jj] - mn);
                rs += e;
                PsT[(c0 + jj) * 68 + r0 + i] = e;
            }
#pragma unroll
            for (int off = 8; off >= 1; off >>= 1)
                rs += __shfl_xor_sync(0xffffffffu, rs, off, 16);
            lrow[i] = lrow[i] * sc + rs;
#pragma unroll
            for (int c = 0; c < 8; ++c) Oa[i][c] *= sc;
        }
        __syncthreads();

#pragma unroll 2
        for (int kv = 0; kv < 64; ++kv) {
            float4 a4 = *(const float4*)&PsT[kv * 68 + r0];
            float av[4] = {a4.x, a4.y, a4.z, a4.w};
            float4 b0 = *(const float4*)&Vs[kv * 128 + oc0];
            float4 b1 = *(const float4*)&Vs[kv * 128 + oc0 + 4];
            float bv[8] = {b0.x, b0.y, b0.z, b0.w, b1.x, b1.y, b1.z, b1.w};
#pragma unroll
            for (int i = 0; i < 4; ++i)
#pragma unroll
                for (int c = 0; c < 8; ++c)
                    Oa[i][c] += av[i] * bv[c];
        }
    }

#pragma unroll
    for (int i = 0; i < 4; ++i) {
        float inv = 1.f / lrow[i];
        size_t base = (size_t)(rowbase + qt * 64 + r0 + i) * 2048 + h * 128 + oc0;
#pragma unroll
        for (int c = 0; c < 8; ++c)
            Od[base + c] = Oa[i][c] * inv;
    }
}

// ---------------- per-segment memory outer product ----------------
__global__ __launch_bounds__(256) void pmat_k(
    const float* __restrict__ Kg, const float* __restrict__ Vg, float* __restrict__ P)
{
    __shared__ float sk[16][128];
    __shared__ float sv[16][128];
    const int tid = threadIdx.x;
    const int ty = tid >> 4, tx = tid & 15;
    const int seg = blockIdx.x, bh = blockIdx.y;
    const int b = bh >> 4, h = bh & 15;
    const int rowbase = b * 4096 + seg * 512;
    float acc[8][8] = {};

    for (int ck = 0; ck < 512; ck += 16) {
        __syncthreads();
#pragma unroll
        for (int u = 0; u < 2; ++u) {
            int fi = tid + u * 256;
            int r = fi >> 5;
            int c = (fi & 31) << 2;
            size_t gi = (size_t)(rowbase + ck + r) * 6144 + h * 128 + c;
            float4 kv = *(const float4*)&Kg[gi];
            float4 e;
            e.x = kv.x > 0.f ? kv.x + 1.f : expf(kv.x);
            e.y = kv.y > 0.f ? kv.y + 1.f : expf(kv.y);
            e.z = kv.z > 0.f ? kv.z + 1.f : expf(kv.z);
            e.w = kv.w > 0.f ? kv.w + 1.f : expf(kv.w);
            *(float4*)&sk[r][c] = e;
            *(float4*)&sv[r][c] = *(const float4*)&Vg[gi];
        }
        __syncthreads();
#pragma unroll
        for (int s = 0; s < 16; ++s) {
            float av[8], bv[8];
            *(float4*)&av[0] = *(const float4*)&sk[s][ty * 8];
            *(float4*)&av[4] = *(const float4*)&sk[s][ty * 8 + 4];
            *(float4*)&bv[0] = *(const float4*)&sv[s][tx * 8];
            *(float4*)&bv[4] = *(const float4*)&sv[s][tx * 8 + 4];
#pragma unroll
            for (int i = 0; i < 8; ++i)
#pragma unroll
                for (int j = 0; j < 8; ++j)
                    acc[i][j] += av[i] * bv[j];
        }
    }

    float* Pp = P + ((size_t)bh * 8 + seg) * 16384;
#pragma unroll
    for (int i = 0; i < 8; ++i)
#pragma unroll
        for (int j = 0; j < 8; ++j)
            Pp[(ty * 8 + i) * 128 + tx * 8 + j] = acc[i][j];
}

// ---------------- z_i = sum elu(k)+1 ----------------
__global__ void zsum_k(const float* __restrict__ Kg, float* __restrict__ z)
{
    int d = threadIdx.x;
    int seg = blockIdx.x, bh = blockIdx.y;
    int b = bh >> 4, h = bh & 15;
    const float* Kp = Kg + (size_t)(b * 4096 + seg * 512) * 6144 + h * 128 + d;
    float s = 0.f;
    for (int i = 0; i < 512; ++i) {
        float x = Kp[(size_t)i * 6144];
        s += x > 0.f ? x + 1.f : expf(x);
    }
    z[((size_t)bh * 8 + seg) * 128 + d] = s;
}

// ---------------- exclusive prefix over segments ----------------
__global__ void prefix_k(const float* __restrict__ P, const float* __restrict__ z,
                         float* __restrict__ Mpre, float* __restrict__ zpre)
{
    int bh = blockIdx.x;
    int tid = threadIdx.x;
    for (int idx = tid; idx < 16384; idx += 256) {
        float run = 0.f;
        for (int s = 0; s < 8; ++s) {
            size_t o = ((size_t)bh * 8 + s) * 16384 + idx;
            Mpre[o] = run;
            run += P[o];
        }
    }
    if (tid < 128) {
        float run = 1.f / 128.f;
        for (int s = 0; s < 8; ++s) {
            size_t o = ((size_t)bh * 8 + s) * 128 + tid;
            zpre[o] = run;
            run += z[o];
        }
    }
}

// ---------------- att_mem + gated blend ----------------
__global__ __launch_bounds__(256) void combine_k(
    const float* __restrict__ Q, const float* __restrict__ Mpre,
    const float* __restrict__ zpre, const float* __restrict__ attdot,
    const float* __restrict__ betas, float* __restrict__ att)
{
    extern __shared__ float sm[];
    float* sqT = sm;
    float* Ms  = sqT + 128 * 64;
    float* zs  = Ms + 128 * 128;

    const int tid = threadIdx.x;
    const int ty = tid >> 4, tx = tid & 15;
    const int bh = blockIdx.z, b = bh >> 4, h = bh & 15;
    const int seg = blockIdx.y, qt = blockIdx.x;
    const int rowbase = b * 4096 + seg * 512;

#pragma unroll
    for (int u = 0; u < 8; ++u) {
        int fi = tid + u * 256;
        int r = fi >> 5;
        int c = (fi & 31) << 2;
        float4 v = *(const float4*)&Q[(size_t)(rowbase + qt * 64 + r) * 6144 + h * 128 + c];
        sqT[(c + 0) * 64 + r] = v.x > 0.f ? v.x + 1.f : expf(v.x);
        sqT[(c + 1) * 64 + r] = v.y > 0.f ? v.y + 1.f : expf(v.y);
        sqT[(c + 2) * 64 + r] = v.z > 0.f ? v.z + 1.f : expf(v.z);
        sqT[(c + 3) * 64 + r] = v.w > 0.f ? v.w + 1.f : expf(v.w);
    }
    {
        const float4* Mg = (const float4*)(Mpre + ((size_t)bh * 8 + seg) * 16384);
        float4* Ms4 = (float4*)Ms;
        for (int i = tid; i < 4096; i += 256) Ms4[i] = Mg[i];
        if (tid < 128) zs[tid] = zpre[((size_t)bh * 8 + seg) * 128 + tid];
    }
    __syncthreads();

    const int r0 = ty * 4, oc0 = tx * 8;
    float acc[4][8] = {};
    float den[4] = {};
#pragma unroll 4
    for (int k = 0; k < 128; ++k) {
        float4 a4 = *(const float4*)&sqT[k * 64 + r0];
        float av[4] = {a4.x, a4.y, a4.z, a4.w};
        float zk = zs[k];
        float4 b0 = *(const float4*)&Ms[k * 128 + oc0];
        float4 b1 = *(const float4*)&Ms[k * 128 + oc0 + 4];
        float bv[8] = {b0.x, b0.y, b0.z, b0.w, b1.x, b1.y, b1.z, b1.w};
#pragma unroll
        for (int i = 0; i < 4; ++i) {
            den[i] += av[i] * zk;
#pragma unroll
            for (int c = 0; c < 8; ++c)
                acc[i][c] += av[i] * bv[c];
        }
    }

#pragma unroll
    for (int i = 0; i < 4; ++i) {
        float inv = 1.f / den[i];
        size_t base = (size_t)(rowbase + qt * 64 + r0 + i) * 2048 + h * 128 + oc0;
#pragma unroll
        for (int c = 0; c < 8; ++c) {
            float g = 1.f / (1.f + expf(-betas[h * 128 + oc0 + c]));
            float am = acc[i][c] * inv;
            float ad = attdot[base + c];
            att[base + c] = g * am + (1.f - g) * ad;
        }
    }
}

// ---------------- residual + LayerNorm ----------------
__global__ __launch_bounds__(256) void ln_k(
    const float* __restrict__ y, const float* __restrict__ x,
    const float* __restrict__ gm, const float* __restrict__ bt,
    float* __restrict__ out)
{
    __shared__ float r1[8], r2[8];
    const int row = blockIdx.x, tid = threadIdx.x;
    const float* yp = y + (size_t)row * 2048;
    const float* xp = x + (size_t)row * 2048;
    float s1 = 0.f, s2 = 0.f;
    for (int c = tid; c < 2048; c += 256) {
        float v = yp[c] + xp[c];
        s1 += v; s2 += v * v;
    }
#pragma unroll
    for (int off = 16; off >= 1; off >>= 1) {
        s1 += __shfl_xor_sync(0xffffffffu, s1, off);
        s2 += __shfl_xor_sync(0xffffffffu, s2, off);
    }
    if ((tid & 31) == 0) { r1[tid >> 5] = s1; r2[tid >> 5] = s2; }
    __syncthreads();
    if (tid == 0) {
        float a = 0.f, bb = 0.f;
        for (int w = 0; w < 8; ++w) { a += r1[w]; bb += r2[w]; }
        r1[0] = a; r2[0] = bb;
    }
    __syncthreads();
    const float mu = r1[0] * (1.f / 2048.f);
    const float var = r2[0] * (1.f / 2048.f) - mu * mu;
    const float rs = rsqrtf(var + 1e-5f);
    for (int c = tid; c < 2048; c += 256) {
        float v = yp[c] + xp[c];
        out[(size_t)row * 2048 + c] = (v - mu) * rs * gm[c] + bt[c];
    }
}

// ---------------- host ----------------
extern "C" void kernel_launch(void* const* d_in, const int* in_sizes, int n_in,
                              void* d_out, int out_size)
{
    const float* x     = (const float*)d_in[0];
    const float* Wq    = (const float*)d_in[1];
    const float* Wk    = (const float*)d_in[2];
    const float* Wv    = (const float*)d_in[3];
    const float* Wo    = (const float*)d_in[4];
    const float* betas = (const float*)d_in[5];
    const float* W1    = (const float*)d_in[6];
    const float* b1    = (const float*)d_in[7];
    const float* W2    = (const float*)d_in[8];
    const float* b2    = (const float*)d_in[9];
    const float* lng   = (const float*)d_in[10];
    const float* lnb   = (const float*)d_in[11];
    float* out = (float*)d_out;

    float *QKV, *AD, *AT, *Pb, *Mp, *zb, *zp, *AO, *HB, *YB;
    float *WqkvT, *WoT, *W1T, *W2T;
    cudaGetSymbolAddress((void**)&QKV, g_qkv);
    cudaGetSymbolAddress((void**)&AD, g_attdot);
    cudaGetSymbolAddress((void**)&AT, g_att);
    cudaGetSymbolAddress((void**)&Pb, g_P);
    cudaGetSymbolAddress((void**)&Mp, g_Mpre);
    cudaGetSymbolAddress((void**)&zb, g_zz);
    cudaGetSymbolAddress((void**)&zp, g_zpre);
    cudaGetSymbolAddress((void**)&AO, g_ao);
    cudaGetSymbolAddress((void**)&HB, g_hb);
    cudaGetSymbolAddress((void**)&YB, g_yb);
    cudaGetSymbolAddress((void**)&WqkvT, g_WqkvT);
    cudaGetSymbolAddress((void**)&WoT, g_WoT);
    cudaGetSymbolAddress((void**)&W1T, g_W1T);
    cudaGetSymbolAddress((void**)&W2T, g_W2T);

    const float* Qb = QKV;
    const float* Kb = QKV + 2048;
    const float* Vb = QKV + 4096;

    const int ATT_SMEM = (128 * 64 + 128 * 64 + 64 * 128 + 64 * 68) * 4;
    const int CMB_SMEM = (128 * 64 + 128 * 128 + 128) * 4;
    cudaFuncSetAttribute(attdot_k, cudaFuncAttributeMaxDynamicSharedMemorySize, ATT_SMEM);
    cudaFuncSetAttribute(combine_k, cudaFuncAttributeMaxDynamicSharedMemorySize, CMB_SMEM);
    cudaFuncSetAttribute(gemm_mma<false, false>, cudaFuncAttributeMaxDynamicSharedMemorySize, GEMM_SMEM);
    cudaFuncSetAttribute(gemm_mma<true, true>,   cudaFuncAttributeMaxDynamicSharedMemorySize, GEMM_SMEM);
    cudaFuncSetAttribute(gemm_mma<true, false>,  cudaFuncAttributeMaxDynamicSharedMemorySize, GEMM_SMEM);

    // ---- weight transposes (K-major B operands, RNA-rounded to tf32) ----
    transpose_k<<<dim3(64, 64), 256>>>(Wq, WqkvT, 2048, 2048);
    transpose_k<<<dim3(64, 64), 256>>>(Wk, WqkvT + 2048 * 2048, 2048, 2048);
    transpose_k<<<dim3(64, 64), 256>>>(Wv, WqkvT + 2 * 2048 * 2048, 2048, 2048);
    transpose_k<<<dim3(64, 64), 256>>>(Wo, WoT, 2048, 2048);
    transpose_k<<<dim3(256, 64), 256>>>(W1, W1T, 2048, 8192);
    transpose_k<<<dim3(64, 256), 256>>>(W2, W2T, 8192, 2048);

    // ---- fused QKV projection ----
    gemm_mma<false, false><<<dim3(48, 64), 256, GEMM_SMEM>>>(x, WqkvT, nullptr, QKV, 6144, 2048);

    // ---- attention ----
    dim3 ga(8, 8, 32);
    attdot_k<<<ga, 256, ATT_SMEM>>>(Qb, Kb, Vb, AD);
    dim3 gz(8, 32);
    zsum_k<<<gz, 128>>>(Kb, zb);
    pmat_k<<<gz, 256>>>(Kb, Vb, Pb);
    prefix_k<<<32, 256>>>(Pb, zb, Mp, zp);
    combine_k<<<ga, 256, CMB_SMEM>>>(Qb, Mp, zp, AD, betas, AT);

    // ---- output projection + MLP ----
    gemm_mma<false, false><<<dim3(16, 64), 256, GEMM_SMEM>>>(AT, WoT, nullptr, AO, 2048, 2048);
    gemm_mma<true, true><<<dim3(64, 64), 256, GEMM_SMEM>>>(AO, W1T, b1, HB, 8192, 2048);
    gemm_mma<true, false><<<dim3(16, 64), 256, GEMM_SMEM>>>(HB, W2T, b2, YB, 2048, 8192);

    // ---- residual + LayerNorm ----
    ln_k<<<8192, 256>>>(YB, x, lng, lnb, out);
}

// round 4
// speedup vs baseline: 4.8644x; 1.8087x over previous
#include <cuda_runtime.h>
#include <cuda_fp16.h>
#include <math.h>
#include <stdint.h>

// ---------------- shapes ----------------
// B=2, S=4096, D=2048, H=16, DK=DV=128, SEG=512, NSEG=8, DH=8192, M=B*S=8192
// QKV fused: stride 6144 (Q at col 0, K at 2048, V at 4096)

// ---------------- scratch ----------------
static __device__ float  g_qkv[8192 * 6144];
static __device__ __half g_xh[8192 * 2048];
static __device__ float  g_attdot[8192 * 2048];
static __device__ __half g_att[8192 * 2048];
static __device__ float  g_P[2 * 16 * 8 * 128 * 128];
static __device__ float  g_Mpre[2 * 16 * 8 * 128 * 128];
static __device__ float  g_zz[2 * 16 * 8 * 128];
static __device__ float  g_zpre[2 * 16 * 8 * 128];
static __device__ __half g_ao[8192 * 2048];
static __device__ __half g_hb[8192 * 8192];
static __device__ float  g_yb[8192 * 2048];
static __device__ __half g_WqkvT[6144 * 2048];
static __device__ __half g_WoT[2048 * 2048];
static __device__ __half g_W1T[8192 * 2048];
static __device__ __half g_W2T[2048 * 8192];

// ---------------- helpers ----------------
__device__ __forceinline__ uint32_t smem_u32(const void* p) {
    uint32_t a;
    asm("{ .reg .u64 t; cvta.to.shared.u64 t, %1; cvt.u32.u64 %0, t; }" : "=r"(a) : "l"(p));
    return a;
}
__device__ __forceinline__ void cp16(uint32_t dst, const void* src) {
    asm volatile("cp.async.cg.shared.global [%0], [%1], 16;" :: "r"(dst), "l"(src) : "memory");
}
__device__ __forceinline__ void mma_f16(float* c, const uint32_t* a, const uint32_t* b) {
    asm volatile("mma.sync.aligned.m16n8k16.row.col.f32.f16.f16.f32 "
        "{%0,%1,%2,%3}, {%4,%5,%6,%7}, {%8,%9}, {%0,%1,%2,%3};"
        : "+f"(c[0]), "+f"(c[1]), "+f"(c[2]), "+f"(c[3])
        : "r"(a[0]), "r"(a[1]), "r"(a[2]), "r"(a[3]), "r"(b[0]), "r"(b[1]));
}

// ---------------- fp16 tensor-core GEMM: C[M,N] = A[M,K] @ Bt[N,K]^T ----------------
// CTA tile 128x128, BK=32 halves, 256 threads, 3-stage cp.async pipeline.
// smem row stride 40 halves -> conflict-free half2 fragment loads.
#define GSTAGE_H 10240                   // halves per stage (As 5120 + Bs 5120)
#define GEMM_SMEM (3 * GSTAGE_H * 2)     // 61440 bytes

template <bool BIAS, bool RELU, typename OUTT>
__global__ __launch_bounds__(256, 2) void gemm_mma(
    const __half* __restrict__ A, const __half* __restrict__ Bt,
    const float* __restrict__ bias, OUTT* __restrict__ C,
    int Nn, int K)
{
    extern __shared__ __half smh[];
    const int tid = threadIdx.x;
    const int wid = tid >> 5, lane = tid & 31;
    const int group = lane >> 2, tig = lane & 3;
    const int wm = wid >> 2, wn = wid & 3;
    const int m0 = blockIdx.y * 128, n0 = blockIdx.x * 128;
    const int nt = K >> 5;

    const int lrow = tid >> 2;            // 0..63
    const int lc   = (tid & 3) << 3;      // 0,8,16,24 (halves)

    // ---- preload stages 0,1 ----
#pragma unroll
    for (int t = 0; t < 2; ++t) {
        __half* As = smh + t * GSTAGE_H;
        __half* Bs = As + 5120;
        const int k0 = t * 32;
#pragma unroll
        for (int j = 0; j < 2; ++j) {
            int row = lrow + j * 64;
            cp16(smem_u32(As + row * 40 + lc), A + (size_t)(m0 + row) * K + k0 + lc);
            cp16(smem_u32(Bs + row * 40 + lc), Bt + (size_t)(n0 + row) * K + k0 + lc);
        }
        asm volatile("cp.async.commit_group;" ::: "memory");
    }

    float acc[4][4][4] = {};

    for (int t = 0; t < nt; ++t) {
        asm volatile("cp.async.wait_group 1;" ::: "memory");
        __syncthreads();

        if (t + 2 < nt) {
            const int s = (t + 2) % 3;
            __half* As = smh + s * GSTAGE_H;
            __half* Bs = As + 5120;
            const int k0 = (t + 2) * 32;
#pragma unroll
            for (int j = 0; j < 2; ++j) {
                int row = lrow + j * 64;
                cp16(smem_u32(As + row * 40 + lc), A + (size_t)(m0 + row) * K + k0 + lc);
                cp16(smem_u32(Bs + row * 40 + lc), Bt + (size_t)(n0 + row) * K + k0 + lc);
            }
        }
        asm volatile("cp.async.commit_group;" ::: "memory");

        const __half* As = smh + (t % 3) * GSTAGE_H;
        const __half* Bs = As + 5120;

#pragma unroll
        for (int ks = 0; ks < 2; ++ks) {
            uint32_t af[4][4], bf[4][2];
            const int c = ks * 16 + tig * 2;
#pragma unroll
            for (int mf = 0; mf < 4; ++mf) {
                const int r = wm * 64 + mf * 16 + group;
                af[mf][0] = *(const uint32_t*)&As[r * 40 + c];
                af[mf][1] = *(const uint32_t*)&As[(r + 8) * 40 + c];
                af[mf][2] = *(const uint32_t*)&As[r * 40 + c + 8];
                af[mf][3] = *(const uint32_t*)&As[(r + 8) * 40 + c + 8];
            }
#pragma unroll
            for (int nf = 0; nf < 4; ++nf) {
                const int n = wn * 32 + nf * 8 + group;
                bf[nf][0] = *(const uint32_t*)&Bs[n * 40 + c];
                bf[nf][1] = *(const uint32_t*)&Bs[n * 40 + c + 8];
            }
#pragma unroll
            for (int mf = 0; mf < 4; ++mf)
#pragma unroll
                for (int nf = 0; nf < 4; ++nf)
                    mma_f16(acc[mf][nf], af[mf], bf[nf]);
        }
        __syncthreads();
    }

    // ---- epilogue: registers -> global ----
#pragma unroll
    for (int mf = 0; mf < 4; ++mf) {
        const int row = m0 + wm * 64 + mf * 16 + group;
#pragma unroll
        for (int nf = 0; nf < 4; ++nf) {
            const int col = n0 + wn * 32 + nf * 8 + 2 * tig;
            float2 v0 = make_float2(acc[mf][nf][0], acc[mf][nf][1]);
            float2 v1 = make_float2(acc[mf][nf][2], acc[mf][nf][3]);
            if (BIAS) {
                float b0 = bias[col], b1 = bias[col + 1];
                v0.x += b0; v0.y += b1; v1.x += b0; v1.y += b1;
            }
            if (RELU) {
                v0.x = fmaxf(v0.x, 0.f); v0.y = fmaxf(v0.y, 0.f);
                v1.x = fmaxf(v1.x, 0.f); v1.y = fmaxf(v1.y, 0.f);
            }
            if constexpr (sizeof(OUTT) == 4) {
                *(float2*)&C[(size_t)row * Nn + col] = v0;
                *(float2*)&C[(size_t)(row + 8) * Nn + col] = v1;
            } else {
                *(__half2*)&C[(size_t)row * Nn + col] = __floats2half2_rn(v0.x, v0.y);
                *(__half2*)&C[(size_t)(row + 8) * Nn + col] = __floats2half2_rn(v1.x, v1.y);
            }
        }
    }
}

// ---------------- fp32 -> fp16 convert ----------------
__global__ __launch_bounds__(256) void cvt_h(const float* __restrict__ S, __half* __restrict__ D)
{
    const size_t i = ((size_t)blockIdx.x * 256 + threadIdx.x) * 8;
    float4 a = *(const float4*)&S[i];
    float4 b = *(const float4*)&S[i + 4];
    __half2 h[4] = {
        __floats2half2_rn(a.x, a.y), __floats2half2_rn(a.z, a.w),
        __floats2half2_rn(b.x, b.y), __floats2half2_rn(b.z, b.w)
    };
    *(uint4*)&D[i] = *(uint4*)h;
}

// ---------------- weight transpose -> fp16 ----------------
__global__ __launch_bounds__(256) void transpose_h(
    const float* __restrict__ S, __half* __restrict__ D, int R, int C)
{
    __shared__ float t[32][33];
    const int bx = blockIdx.x * 32, by = blockIdx.y * 32;
    const int lx = threadIdx.x & 31, ly = threadIdx.x >> 5;
#pragma unroll
    for (int i = 0; i < 32; i += 8)
        t[ly + i][lx] = S[(size_t)(by + ly + i) * C + bx + lx];
    __syncthreads();
#pragma unroll
    for (int i = 0; i < 32; i += 8)
        D[(size_t)(bx + ly + i) * R + by + lx] = __float2half(t[lx][ly + i]);
}

// ---------------- intra-segment causal flash attention (fp32) ----------------
__global__ __launch_bounds__(256) void attdot_k(
    const float* __restrict__ Q, const float* __restrict__ Kg,
    const float* __restrict__ Vg, float* __restrict__ Od)
{
    extern __shared__ float sm[];
    float* QsT = sm;
    float* KsT = QsT + 128 * 64;
    float* Vs  = KsT + 128 * 64;
    float* PsT = Vs + 64 * 128;

    const int tid = threadIdx.x;
    const int ty = tid >> 4, tx = tid & 15;
    const int bh = blockIdx.z;
    const int b = bh >> 4, h = bh & 15;
    const int seg = blockIdx.y, qt = blockIdx.x;
    const int rowbase = b * 4096 + seg * 512;
    const float scale = 0.08838834764831845f;

#pragma unroll
    for (int u = 0; u < 8; ++u) {
        int fi = tid + u * 256;
        int r = fi >> 5;
        int c = (fi & 31) << 2;
        float4 v = *(const float4*)&Q[(size_t)(rowbase + qt * 64 + r) * 6144 + h * 128 + c];
        QsT[(c + 0) * 64 + r] = v.x * scale;
        QsT[(c + 1) * 64 + r] = v.y * scale;
        QsT[(c + 2) * 64 + r] = v.z * scale;
        QsT[(c + 3) * 64 + r] = v.w * scale;
    }

    float Oa[4][8] = {};
    float mrow[4] = {-INFINITY, -INFINITY, -INFINITY, -INFINITY};
    float lrow[4] = {};

    const int r0 = ty * 4, c0 = tx * 4, oc0 = tx * 8;

    for (int j = 0; j <= qt; ++j) {
        __syncthreads();
#pragma unroll
        for (int u = 0; u < 8; ++u) {
            int fi = tid + u * 256;
            int r = fi >> 5;
            int c = (fi & 31) << 2;
            size_t gi = (size_t)(rowbase + j * 64 + r) * 6144 + h * 128 + c;
            float4 kv = *(const float4*)&Kg[gi];
            KsT[(c + 0) * 64 + r] = kv.x;
            KsT[(c + 1) * 64 + r] = kv.y;
            KsT[(c + 2) * 64 + r] = kv.z;
            KsT[(c + 3) * 64 + r] = kv.w;
            *(float4*)&Vs[r * 128 + c] = *(const float4*)&Vg[gi];
        }
        __syncthreads();

        float s[4][4] = {};
#pragma unroll 4
        for (int k = 0; k < 128; ++k) {
            float4 a4 = *(const float4*)&QsT[k * 64 + r0];
            float4 b4 = *(const float4*)&KsT[k * 64 + c0];
            float av[4] = {a4.x, a4.y, a4.z, a4.w};
            float bv[4] = {b4.x, b4.y, b4.z, b4.w};
#pragma unroll
            for (int i = 0; i < 4; ++i)
#pragma unroll
                for (int jj = 0; jj < 4; ++jj)
                    s[i][jj] += av[i] * bv[jj];
        }

        if (j == qt) {
#pragma unroll
            for (int i = 0; i < 4; ++i)
#pragma unroll
                for (int jj = 0; jj < 4; ++jj)
                    if (c0 + jj > r0 + i) s[i][jj] = -INFINITY;
        }

#pragma unroll
        for (int i = 0; i < 4; ++i) {
            float rm = fmaxf(fmaxf(s[i][0], s[i][1]), fmaxf(s[i][2], s[i][3]));
#pragma unroll
            for (int off = 8; off >= 1; off >>= 1)
                rm = fmaxf(rm, __shfl_xor_sync(0xffffffffu, rm, off, 16));
            float mn = fmaxf(mrow[i], rm);
            float sc = expf(mrow[i] - mn);
            mrow[i] = mn;
            float rs = 0.f;
#pragma unroll
            for (int jj = 0; jj < 4; ++jj) {
                float e = expf(s[i][jj] - mn);
                rs += e;
                PsT[(c0 + jj) * 68 + r0 + i] = e;
            }
#pragma unroll
            for (int off = 8; off >= 1; off >>= 1)
                rs += __shfl_xor_sync(0xffffffffu, rs, off, 16);
            lrow[i] = lrow[i] * sc + rs;
#pragma unroll
            for (int c = 0; c < 8; ++c) Oa[i][c] *= sc;
        }
        __syncthreads();

#pragma unroll 2
        for (int kv = 0; kv < 64; ++kv) {
            float4 a4 = *(const float4*)&PsT[kv * 68 + r0];
            float av[4] = {a4.x, a4.y, a4.z, a4.w};
            float4 b0 = *(const float4*)&Vs[kv * 128 + oc0];
            float4 b1 = *(const float4*)&Vs[kv * 128 + oc0 + 4];
            float bv[8] = {b0.x, b0.y, b0.z, b0.w, b1.x, b1.y, b1.z, b1.w};
#pragma unroll
            for (int i = 0; i < 4; ++i)
#pragma unroll
                for (int c = 0; c < 8; ++c)
                    Oa[i][c] += av[i] * bv[c];
        }
    }

#pragma unroll
    for (int i = 0; i < 4; ++i) {
        float inv = 1.f / lrow[i];
        size_t base = (size_t)(rowbase + qt * 64 + r0 + i) * 2048 + h * 128 + oc0;
#pragma unroll
        for (int c = 0; c < 8; ++c)
            Od[base + c] = Oa[i][c] * inv;
    }
}

// ---------------- per-segment memory outer product ----------------
__global__ __launch_bounds__(256) void pmat_k(
    const float* __restrict__ Kg, const float* __restrict__ Vg, float* __restrict__ P)
{
    __shared__ float sk[16][128];
    __shared__ float sv[16][128];
    const int tid = threadIdx.x;
    const int ty = tid >> 4, tx = tid & 15;
    const int seg = blockIdx.x, bh = blockIdx.y;
    const int b = bh >> 4, h = bh & 15;
    const int rowbase = b * 4096 + seg * 512;
    float acc[8][8] = {};

    for (int ck = 0; ck < 512; ck += 16) {
        __syncthreads();
#pragma unroll
        for (int u = 0; u < 2; ++u) {
            int fi = tid + u * 256;
            int r = fi >> 5;
            int c = (fi & 31) << 2;
            size_t gi = (size_t)(rowbase + ck + r) * 6144 + h * 128 + c;
            float4 kv = *(const float4*)&Kg[gi];
            float4 e;
            e.x = kv.x > 0.f ? kv.x + 1.f : expf(kv.x);
            e.y = kv.y > 0.f ? kv.y + 1.f : expf(kv.y);
            e.z = kv.z > 0.f ? kv.z + 1.f : expf(kv.z);
            e.w = kv.w > 0.f ? kv.w + 1.f : expf(kv.w);
            *(float4*)&sk[r][c] = e;
            *(float4*)&sv[r][c] = *(const float4*)&Vg[gi];
        }
        __syncthreads();
#pragma unroll
        for (int s = 0; s < 16; ++s) {
            float av[8], bv[8];
            *(float4*)&av[0] = *(const float4*)&sk[s][ty * 8];
            *(float4*)&av[4] = *(const float4*)&sk[s][ty * 8 + 4];
            *(float4*)&bv[0] = *(const float4*)&sv[s][tx * 8];
            *(float4*)&bv[4] = *(const float4*)&sv[s][tx * 8 + 4];
#pragma unroll
            for (int i = 0; i < 8; ++i)
#pragma unroll
                for (int j = 0; j < 8; ++j)
                    acc[i][j] += av[i] * bv[j];
        }
    }

    float* Pp = P + ((size_t)bh * 8 + seg) * 16384;
#pragma unroll
    for (int i = 0; i < 8; ++i)
#pragma unroll
        for (int j = 0; j < 8; ++j)
            Pp[(ty * 8 + i) * 128 + tx * 8 + j] = acc[i][j];
}

// ---------------- z_i = sum elu(k)+1 ----------------
__global__ void zsum_k(const float* __restrict__ Kg, float* __restrict__ z)
{
    int d = threadIdx.x;
    int seg = blockIdx.x, bh = blockIdx.y;
    int b = bh >> 4, h = bh & 15;
    const float* Kp = Kg + (size_t)(b * 4096 + seg * 512) * 6144 + h * 128 + d;
    float s = 0.f;
    for (int i = 0; i < 512; ++i) {
        float x = Kp[(size_t)i * 6144];
        s += x > 0.f ? x + 1.f : expf(x);
    }
    z[((size_t)bh * 8 + seg) * 128 + d] = s;
}

// ---------------- exclusive prefix over segments ----------------
__global__ void prefix_k(const float* __restrict__ P, const float* __restrict__ z,
                         float* __restrict__ Mpre, float* __restrict__ zpre)
{
    int bh = blockIdx.x;
    int tid = threadIdx.x;
    for (int idx = tid; idx < 16384; idx += 256) {
        float run = 0.f;
        for (int s = 0; s < 8; ++s) {
            size_t o = ((size_t)bh * 8 + s) * 16384 + idx;
            Mpre[o] = run;
            run += P[o];
        }
    }
    if (tid < 128) {
        float run = 1.f / 128.f;
        for (int s = 0; s < 8; ++s) {
            size_t o = ((size_t)bh * 8 + s) * 128 + tid;
            zpre[o] = run;
            run += z[o];
        }
    }
}

// ---------------- att_mem + gated blend (writes half for Wo GEMM) ----------------
__global__ __launch_bounds__(256) void combine_k(
    const float* __restrict__ Q, const float* __restrict__ Mpre,
    const float* __restrict__ zpre, const float* __restrict__ attdot,
    const float* __restrict__ betas, __half* __restrict__ att)
{
    extern __shared__ float sm[];
    float* sqT = sm;
    float* Ms  = sqT + 128 * 64;
    float* zs  = Ms + 128 * 128;

    const int tid = threadIdx.x;
    const int ty = tid >> 4, tx = tid & 15;
    const int bh = blockIdx.z, b = bh >> 4, h = bh & 15;
    const int seg = blockIdx.y, qt = blockIdx.x;
    const int rowbase = b * 4096 + seg * 512;

#pragma unroll
    for (int u = 0; u < 8; ++u) {
        int fi = tid + u * 256;
        int r = fi >> 5;
        int c = (fi & 31) << 2;
        float4 v = *(const float4*)&Q[(size_t)(rowbase + qt * 64 + r) * 6144 + h * 128 + c];
        sqT[(c + 0) * 64 + r] = v.x > 0.f ? v.x + 1.f : expf(v.x);
        sqT[(c + 1) * 64 + r] = v.y > 0.f ? v.y + 1.f : expf(v.y);
        sqT[(c + 2) * 64 + r] = v.z > 0.f ? v.z + 1.f : expf(v.z);
        sqT[(c + 3) * 64 + r] = v.w > 0.f ? v.w + 1.f : expf(v.w);
    }
    {
        const float4* Mg = (const float4*)(Mpre + ((size_t)bh * 8 + seg) * 16384);
        float4* Ms4 = (float4*)Ms;
        for (int i = tid; i < 4096; i += 256) Ms4[i] = Mg[i];
        if (tid < 128) zs[tid] = zpre[((size_t)bh * 8 + seg) * 128 + tid];
    }
    __syncthreads();

    const int r0 = ty * 4, oc0 = tx * 8;
    float acc[4][8] = {};
    float den[4] = {};
#pragma unroll 4
    for (int k = 0; k < 128; ++k) {
        float4 a4 = *(const float4*)&sqT[k * 64 + r0];
        float av[4] = {a4.x, a4.y, a4.z, a4.w};
        float zk = zs[k];
        float4 b0 = *(const float4*)&Ms[k * 128 + oc0];
        float4 b1 = *(const float4*)&Ms[k * 128 + oc0 + 4];
        float bv[8] = {b0.x, b0.y, b0.z, b0.w, b1.x, b1.y, b1.z, b1.w};
#pragma unroll
        for (int i = 0; i < 4; ++i) {
            den[i] += av[i] * zk;
#pragma unroll
            for (int c = 0; c < 8; ++c)
                acc[i][c] += av[i] * bv[c];
        }
    }

#pragma unroll
    for (int i = 0; i < 4; ++i) {
        float inv = 1.f / den[i];
        size_t base = (size_t)(rowbase + qt * 64 + r0 + i) * 2048 + h * 128 + oc0;
#pragma unroll
        for (int c = 0; c < 8; c += 2) {
            float g0 = 1.f / (1.f + expf(-betas[h * 128 + oc0 + c]));
            float g1 = 1.f / (1.f + expf(-betas[h * 128 + oc0 + c + 1]));
            float o0 = g0 * (acc[i][c] * inv)     + (1.f - g0) * attdot[base + c];
            float o1 = g1 * (acc[i][c + 1] * inv) + (1.f - g1) * attdot[base + c + 1];
            *(__half2*)&att[base + c] = __floats2half2_rn(o0, o1);
        }
    }
}

// ---------------- residual + LayerNorm ----------------
__global__ __launch_bounds__(256) void ln_k(
    const float* __restrict__ y, const float* __restrict__ x,
    const float* __restrict__ gm, const float* __restrict__ bt,
    float* __restrict__ out)
{
    __shared__ float r1[8], r2[8];
    const int row = blockIdx.x, tid = threadIdx.x;
    const float* yp = y + (size_t)row * 2048;
    const float* xp = x + (size_t)row * 2048;
    float s1 = 0.f, s2 = 0.f;
    for (int c = tid; c < 2048; c += 256) {
        float v = yp[c] + xp[c];
        s1 += v; s2 += v * v;
    }
#pragma unroll
    for (int off = 16; off >= 1; off >>= 1) {
        s1 += __shfl_xor_sync(0xffffffffu, s1, off);
        s2 += __shfl_xor_sync(0xffffffffu, s2, off);
    }
    if ((tid & 31) == 0) { r1[tid >> 5] = s1; r2[tid >> 5] = s2; }
    __syncthreads();
    if (tid == 0) {
        float a = 0.f, bb = 0.f;
        for (int w = 0; w < 8; ++w) { a += r1[w]; bb += r2[w]; }
        r1[0] = a; r2[0] = bb;
    }
    __syncthreads();
    const float mu = r1[0] * (1.f / 2048.f);
    const float var = r2[0] * (1.f / 2048.f) - mu * mu;
    const float rs = rsqrtf(var + 1e-5f);
    for (int c = tid; c < 2048; c += 256) {
        float v = yp[c] + xp[c];
        out[(size_t)row * 2048 + c] = (v - mu) * rs * gm[c] + bt[c];
    }
}

// ---------------- host ----------------
extern "C" void kernel_launch(void* const* d_in, const int* in_sizes, int n_in,
                              void* d_out, int out_size)
{
    const float* x     = (const float*)d_in[0];
    const float* Wq    = (const float*)d_in[1];
    const float* Wk    = (const float*)d_in[2];
    const float* Wv    = (const float*)d_in[3];
    const float* Wo    = (const float*)d_in[4];
    const float* betas = (const float*)d_in[5];
    const float* W1    = (const float*)d_in[6];
    const float* b1    = (const float*)d_in[7];
    const float* W2    = (const float*)d_in[8];
    const float* b2    = (const float*)d_in[9];
    const float* lng   = (const float*)d_in[10];
    const float* lnb   = (const float*)d_in[11];
    float* out = (float*)d_out;

    float *QKV, *AD, *Pb, *Mp, *zb, *zp, *YB;
    __half *XH, *AT, *AO, *HB, *WqkvT, *WoT, *W1T, *W2T;
    cudaGetSymbolAddress((void**)&QKV, g_qkv);
    cudaGetSymbolAddress((void**)&XH, g_xh);
    cudaGetSymbolAddress((void**)&AD, g_attdot);
    cudaGetSymbolAddress((void**)&AT, g_att);
    cudaGetSymbolAddress((void**)&Pb, g_P);
    cudaGetSymbolAddress((void**)&Mp, g_Mpre);
    cudaGetSymbolAddress((void**)&zb, g_zz);
    cudaGetSymbolAddress((void**)&zp, g_zpre);
    cudaGetSymbolAddress((void**)&AO, g_ao);
    cudaGetSymbolAddress((void**)&HB, g_hb);
    cudaGetSymbolAddress((void**)&YB, g_yb);
    cudaGetSymbolAddress((void**)&WqkvT, g_WqkvT);
    cudaGetSymbolAddress((void**)&WoT, g_WoT);
    cudaGetSymbolAddress((void**)&W1T, g_W1T);
    cudaGetSymbolAddress((void**)&W2T, g_W2T);

    const float* Qb = QKV;
    const float* Kb = QKV + 2048;
    const float* Vb = QKV + 4096;

    const int ATT_SMEM = (128 * 64 + 128 * 64 + 64 * 128 + 64 * 68) * 4;
    const int CMB_SMEM = (128 * 64 + 128 * 128 + 128) * 4;
    cudaFuncSetAttribute(attdot_k, cudaFuncAttributeMaxDynamicSharedMemorySize, ATT_SMEM);
    cudaFuncSetAttribute(combine_k, cudaFuncAttributeMaxDynamicSharedMemorySize, CMB_SMEM);
    cudaFuncSetAttribute((const void*)gemm_mma<false, false, float>,  cudaFuncAttributeMaxDynamicSharedMemorySize, GEMM_SMEM);
    cudaFuncSetAttribute((const void*)gemm_mma<false, false, __half>, cudaFuncAttributeMaxDynamicSharedMemorySize, GEMM_SMEM);
    cudaFuncSetAttribute((const void*)gemm_mma<true, true, __half>,   cudaFuncAttributeMaxDynamicSharedMemorySize, GEMM_SMEM);
    cudaFuncSetAttribute((const void*)gemm_mma<true, false, float>,   cudaFuncAttributeMaxDynamicSharedMemorySize, GEMM_SMEM);

    // ---- input convert + weight transposes (K-major half B operands) ----
    cvt_h<<<8192, 256>>>(x, XH);
    transpose_h<<<dim3(64, 64), 256>>>(Wq, WqkvT, 2048, 2048);
    transpose_h<<<dim3(64, 64), 256>>>(Wk, WqkvT + 2048 * 2048, 2048, 2048);
    transpose_h<<<dim3(64, 64), 256>>>(Wv, WqkvT + 2 * 2048 * 2048, 2048, 2048);
    transpose_h<<<dim3(64, 64), 256>>>(Wo, WoT, 2048, 2048);
    transpose_h<<<dim3(256, 64), 256>>>(W1, W1T, 2048, 8192);
    transpose_h<<<dim3(64, 256), 256>>>(W2, W2T, 8192, 2048);

    // ---- fused QKV projection (fp32 out for attention) ----
    gemm_mma<false, false, float><<<dim3(48, 64), 256, GEMM_SMEM>>>(XH, WqkvT, nullptr, QKV, 6144, 2048);

    // ---- attention ----
    dim3 ga(8, 8, 32);
    attdot_k<<<ga, 256, ATT_SMEM>>>(Qb, Kb, Vb, AD);
    dim3 gz(8, 32);
    zsum_k<<<gz, 128>>>(Kb, zb);
    pmat_k<<<gz, 256>>>(Kb, Vb, Pb);
    prefix_k<<<32, 256>>>(Pb, zb, Mp, zp);
    combine_k<<<ga, 256, CMB_SMEM>>>(Qb, Mp, zp, AD, betas, AT);

    // ---- output projection + MLP (half intermediates) ----
    gemm_mma<false, false, __half><<<dim3(16, 64), 256, GEMM_SMEM>>>(AT, WoT, nullptr, AO, 2048, 2048);
    gemm_mma<true, true, __half><<<dim3(64, 64), 256, GEMM_SMEM>>>(AO, W1T, b1, HB, 8192, 2048);
    gemm_mma<true, false, float><<<dim3(16, 64), 256, GEMM_SMEM>>>(HB, W2T, b2, YB, 2048, 8192);

    // ---- residual + LayerNorm ----
    ln_k<<<8192, 256>>>(YB, x, lng, lnb, out);
}

// round 5
// speedup vs baseline: 6.1371x; 1.2616x over previous
#include <cuda_runtime.h>
#include <cuda_fp16.h>
#include <math.h>
#include <stdint.h>

// ---------------- shapes ----------------
// B=2, S=4096, D=2048, H=16, DK=DV=128, SEG=512, NSEG=8, DH=8192, M=B*S=8192
// QKV fused (half): stride 6144 (Q at col 0, K at 2048, V at 4096)

// ---------------- scratch ----------------
static __device__ __half g_qkv[8192 * 6144];
static __device__ __half g_xh[8192 * 2048];
static __device__ float  g_attdot[8192 * 2048];
static __device__ __half g_att[8192 * 2048];
static __device__ float  g_P[2 * 16 * 8 * 128 * 128];
static __device__ float  g_Mpre[2 * 16 * 8 * 128 * 128];
static __device__ float  g_zz[2 * 16 * 8 * 128];
static __device__ float  g_zpre[2 * 16 * 8 * 128];
static __device__ __half g_ao[8192 * 2048];
static __device__ __half g_hb[8192 * 8192];
static __device__ float  g_yb[8192 * 2048];
static __device__ __half g_WqkvT[6144 * 2048];
static __device__ __half g_WoT[2048 * 2048];
static __device__ __half g_W1T[8192 * 2048];
static __device__ __half g_W2T[2048 * 8192];

// ---------------- helpers ----------------
__device__ __forceinline__ uint32_t smem_u32(const void* p) {
    uint32_t a;
    asm("{ .reg .u64 t; cvta.to.shared.u64 t, %1; cvt.u32.u64 %0, t; }" : "=r"(a) : "l"(p));
    return a;
}
__device__ __forceinline__ void cp16(uint32_t dst, const void* src) {
    asm volatile("cp.async.cg.shared.global [%0], [%1], 16;" :: "r"(dst), "l"(src) : "memory");
}
__device__ __forceinline__ void mma_f16(float* c, const uint32_t* a, const uint32_t* b) {
    asm volatile("mma.sync.aligned.m16n8k16.row.col.f32.f16.f16.f32 "
        "{%0,%1,%2,%3}, {%4,%5,%6,%7}, {%8,%9}, {%0,%1,%2,%3};"
        : "+f"(c[0]), "+f"(c[1]), "+f"(c[2]), "+f"(c[3])
        : "r"(a[0]), "r"(a[1]), "r"(a[2]), "r"(a[3]), "r"(b[0]), "r"(b[1]));
}
__device__ __forceinline__ uint32_t packh2(float a, float b) {
    __half2 h = __floats2half2_rn(a, b);
    return *(uint32_t*)&h;
}

// ---------------- fp16 tensor-core GEMM: C[M,N] = A[M,K] @ Bt[N,K]^T ----------------
#define GSTAGE_H 10240
#define GEMM_SMEM (3 * GSTAGE_H * 2)

template <bool BIAS, bool RELU, typename OUTT>
__global__ __launch_bounds__(256, 2) void gemm_mma(
    const __half* __restrict__ A, const __half* __restrict__ Bt,
    const float* __restrict__ bias, OUTT* __restrict__ C,
    int Nn, int K)
{
    extern __shared__ __half smh[];
    const int tid = threadIdx.x;
    const int wid = tid >> 5, lane = tid & 31;
    const int group = lane >> 2, tig = lane & 3;
    const int wm = wid >> 2, wn = wid & 3;
    const int m0 = blockIdx.y * 128, n0 = blockIdx.x * 128;
    const int nt = K >> 5;

    const int lrow = tid >> 2;
    const int lc   = (tid & 3) << 3;

#pragma unroll
    for (int t = 0; t < 2; ++t) {
        __half* As = smh + t * GSTAGE_H;
        __half* Bs = As + 5120;
        const int k0 = t * 32;
#pragma unroll
        for (int j = 0; j < 2; ++j) {
            int row = lrow + j * 64;
            cp16(smem_u32(As + row * 40 + lc), A + (size_t)(m0 + row) * K + k0 + lc);
            cp16(smem_u32(Bs + row * 40 + lc), Bt + (size_t)(n0 + row) * K + k0 + lc);
        }
        asm volatile("cp.async.commit_group;" ::: "memory");
    }

    float acc[4][4][4] = {};

    for (int t = 0; t < nt; ++t) {
        asm volatile("cp.async.wait_group 1;" ::: "memory");
        __syncthreads();

        if (t + 2 < nt) {
            const int s = (t + 2) % 3;
            __half* As = smh + s * GSTAGE_H;
            __half* Bs = As + 5120;
            const int k0 = (t + 2) * 32;
#pragma unroll
            for (int j = 0; j < 2; ++j) {
                int row = lrow + j * 64;
                cp16(smem_u32(As + row * 40 + lc), A + (size_t)(m0 + row) * K + k0 + lc);
                cp16(smem_u32(Bs + row * 40 + lc), Bt + (size_t)(n0 + row) * K + k0 + lc);
            }
        }
        asm volatile("cp.async.commit_group;" ::: "memory");

        const __half* As = smh + (t % 3) * GSTAGE_H;
        const __half* Bs = As + 5120;

#pragma unroll
        for (int ks = 0; ks < 2; ++ks) {
            uint32_t af[4][4], bf[4][2];
            const int c = ks * 16 + tig * 2;
#pragma unroll
            for (int mf = 0; mf < 4; ++mf) {
                const int r = wm * 64 + mf * 16 + group;
                af[mf][0] = *(const uint32_t*)&As[r * 40 + c];
                af[mf][1] = *(const uint32_t*)&As[(r + 8) * 40 + c];
                af[mf][2] = *(const uint32_t*)&As[r * 40 + c + 8];
                af[mf][3] = *(const uint32_t*)&As[(r + 8) * 40 + c + 8];
            }
#pragma unroll
            for (int nf = 0; nf < 4; ++nf) {
                const int n = wn * 32 + nf * 8 + group;
                bf[nf][0] = *(const uint32_t*)&Bs[n * 40 + c];
                bf[nf][1] = *(const uint32_t*)&Bs[n * 40 + c + 8];
            }
#pragma unroll
            for (int mf = 0; mf < 4; ++mf)
#pragma unroll
                for (int nf = 0; nf < 4; ++nf)
                    mma_f16(acc[mf][nf], af[mf], bf[nf]);
        }
        __syncthreads();
    }

#pragma unroll
    for (int mf = 0; mf < 4; ++mf) {
        const int row = m0 + wm * 64 + mf * 16 + group;
#pragma unroll
        for (int nf = 0; nf < 4; ++nf) {
            const int col = n0 + wn * 32 + nf * 8 + 2 * tig;
            float2 v0 = make_float2(acc[mf][nf][0], acc[mf][nf][1]);
            float2 v1 = make_float2(acc[mf][nf][2], acc[mf][nf][3]);
            if (BIAS) {
                float b0 = bias[col], b1 = bias[col + 1];
                v0.x += b0; v0.y += b1; v1.x += b0; v1.y += b1;
            }
            if (RELU) {
                v0.x = fmaxf(v0.x, 0.f); v0.y = fmaxf(v0.y, 0.f);
                v1.x = fmaxf(v1.x, 0.f); v1.y = fmaxf(v1.y, 0.f);
            }
            if constexpr (sizeof(OUTT) == 4) {
                *(float2*)&C[(size_t)row * Nn + col] = v0;
                *(float2*)&C[(size_t)(row + 8) * Nn + col] = v1;
            } else {
                *(__half2*)&C[(size_t)row * Nn + col] = __floats2half2_rn(v0.x, v0.y);
                *(__half2*)&C[(size_t)(row + 8) * Nn + col] = __floats2half2_rn(v1.x, v1.y);
            }
        }
    }
}

// ---------------- fp32 -> fp16 convert ----------------
__global__ __launch_bounds__(256) void cvt_h(const float* __restrict__ S, __half* __restrict__ D)
{
    const size_t i = ((size_t)blockIdx.x * 256 + threadIdx.x) * 8;
    float4 a = *(const float4*)&S[i];
    float4 b = *(const float4*)&S[i + 4];
    __half2 h[4] = {
        __floats2half2_rn(a.x, a.y), __floats2half2_rn(a.z, a.w),
        __floats2half2_rn(b.x, b.y), __floats2half2_rn(b.z, b.w)
    };
    *(uint4*)&D[i] = *(uint4*)h;
}

// ---------------- weight transpose -> fp16 ----------------
__global__ __launch_bounds__(256) void transpose_h(
    const float* __restrict__ S, __half* __restrict__ D, int R, int C)
{
    __shared__ float t[32][33];
    const int bx = blockIdx.x * 32, by = blockIdx.y * 32;
    const int lx = threadIdx.x & 31, ly = threadIdx.x >> 5;
#pragma unroll
    for (int i = 0; i < 32; i += 8)
        t[ly + i][lx] = S[(size_t)(by + ly + i) * C + bx + lx];
    __syncthreads();
#pragma unroll
    for (int i = 0; i < 32; i += 8)
        D[(size_t)(bx + ly + i) * R + by + lx] = __float2half(t[lx][ly + i]);
}

// ---------------- tensor-core flash attention (causal, intra-segment) ----------------
// grid (qt=4, seg=8, bh=32), 256 threads. Q tile 128 rows, KV chunks of 64 keys,
// double-buffered cp.async. 8 warps x 16 rows each -> warp-local softmax.
// smem (halves): Qs[128][136] | Ks[2][64][136] | Vs[2][64][136]
#define ATT2_SMEM (52224 * 2)

__global__ __launch_bounds__(256, 1) void attdot_mma(
    const __half* __restrict__ QKVh, float* __restrict__ Od)
{
    extern __shared__ __half smA[];
    __half* Qs = smA;
    const int tid = threadIdx.x;
    const int w = tid >> 5, lane = tid & 31;
    const int group = lane >> 2, tig = lane & 3;
    const int qt = blockIdx.x, seg = blockIdx.y, bh = blockIdx.z;
    const int b = bh >> 4, h = bh & 15;
    const int rowbase = b * 4096 + seg * 512;
    const int nj = 2 * qt + 2;

    // Q tile load (128 rows x 128 halves)
#pragma unroll
    for (int u = 0; u < 8; ++u) {
        int idx = tid + u * 256;
        int r = idx >> 4, c16 = idx & 15;
        cp16(smem_u32(Qs + r * 136 + c16 * 8),
             QKVh + (size_t)(rowbase + qt * 128 + r) * 6144 + h * 128 + c16 * 8);
    }
    // chunk 0 K/V
    {
        __half* Ks = smA + 17408;
        __half* Vs = smA + 34816;
#pragma unroll
        for (int u = 0; u < 4; ++u) {
            int idx = tid + u * 256;
            int r = idx >> 4, c16 = idx & 15;
            size_t gk = (size_t)(rowbase + r) * 6144 + h * 128 + c16 * 8;
            cp16(smem_u32(Ks + r * 136 + c16 * 8), QKVh + 2048 + gk);
            cp16(smem_u32(Vs + r * 136 + c16 * 8), QKVh + 4096 + gk);
        }
    }
    asm volatile("cp.async.commit_group;" ::: "memory");

    float o[16][4];
#pragma unroll
    for (int i = 0; i < 16; ++i)
#pragma unroll
        for (int j2 = 0; j2 < 4; ++j2) o[i][j2] = 0.f;
    float m0 = -1e30f, m1 = -1e30f, l0 = 0.f, l1 = 0.f;
    const float scale = 0.08838834764831845f;
    const int qg0 = qt * 128 + w * 16 + group;

    for (int j = 0; j < nj; ++j) {
        asm volatile("cp.async.wait_group 0;" ::: "memory");
        __syncthreads();
        if (j + 1 < nj) {
            __half* Ks = smA + 17408 + ((j + 1) & 1) * 8704;
            __half* Vs = smA + 34816 + ((j + 1) & 1) * 8704;
#pragma unroll
            for (int u = 0; u < 4; ++u) {
                int idx = tid + u * 256;
                int r = idx >> 4, c16 = idx & 15;
                size_t gk = (size_t)(rowbase + (j + 1) * 64 + r) * 6144 + h * 128 + c16 * 8;
                cp16(smem_u32(Ks + r * 136 + c16 * 8), QKVh + 2048 + gk);
                cp16(smem_u32(Vs + r * 136 + c16 * 8), QKVh + 4096 + gk);
            }
        }
        asm volatile("cp.async.commit_group;" ::: "memory");

        const int kmin = j * 64;
        if (kmin > qt * 128 + w * 16 + 15) continue;   // warp fully above diagonal

        const __half* Ks = smA + 17408 + (j & 1) * 8704;
        const __half* Vs = smA + 34816 + (j & 1) * 8704;

        // ---- scores S[16,64] = Q @ K^T ----
        float c[8][4];
#pragma unroll
        for (int nf = 0; nf < 8; ++nf)
#pragma unroll
            for (int i2 = 0; i2 < 4; ++i2) c[nf][i2] = 0.f;

#pragma unroll
        for (int kt = 0; kt < 8; ++kt) {
            uint32_t qa[4];
            const int qr = w * 16 + group;
            const int qc = kt * 16 + tig * 2;
            qa[0] = *(const uint32_t*)&Qs[qr * 136 + qc];
            qa[1] = *(const uint32_t*)&Qs[(qr + 8) * 136 + qc];
            qa[2] = *(const uint32_t*)&Qs[qr * 136 + qc + 8];
            qa[3] = *(const uint32_t*)&Qs[(qr + 8) * 136 + qc + 8];
#pragma unroll
            for (int nf = 0; nf < 8; ++nf) {
                uint32_t kb[2];
                const int kr = nf * 8 + group;
                kb[0] = *(const uint32_t*)&Ks[kr * 136 + qc];
                kb[1] = *(const uint32_t*)&Ks[kr * 136 + qc + 8];
                mma_f16(c[nf], qa, kb);
            }
        }

        // ---- scale + causal mask (fp32) ----
#pragma unroll
        for (int nf = 0; nf < 8; ++nf)
#pragma unroll
            for (int i2 = 0; i2 < 4; ++i2) c[nf][i2] *= scale;
        if (kmin + 63 > qg0) {
#pragma unroll
            for (int nf = 0; nf < 8; ++nf) {
                const int kc = kmin + nf * 8 + tig * 2;
                if (kc > qg0)         c[nf][0] = -1e30f;
                if (kc + 1 > qg0)     c[nf][1] = -1e30f;
                if (kc > qg0 + 8)     c[nf][2] = -1e30f;
                if (kc + 1 > qg0 + 8) c[nf][3] = -1e30f;
            }
        }

        // ---- online softmax (fp32, warp-local) ----
        float rm0 = -1e30f, rm1 = -1e30f;
#pragma unroll
        for (int nf = 0; nf < 8; ++nf) {
            rm0 = fmaxf(rm0, fmaxf(c[nf][0], c[nf][1]));
            rm1 = fmaxf(rm1, fmaxf(c[nf][2], c[nf][3]));
        }
        rm0 = fmaxf(rm0, __shfl_xor_sync(0xffffffffu, rm0, 1));
        rm0 = fmaxf(rm0, __shfl_xor_sync(0xffffffffu, rm0, 2));
        rm1 = fmaxf(rm1, __shfl_xor_sync(0xffffffffu, rm1, 1));
        rm1 = fmaxf(rm1, __shfl_xor_sync(0xffffffffu, rm1, 2));
        const float mn0 = fmaxf(m0, rm0), mn1 = fmaxf(m1, rm1);
        const float sc0 = __expf(m0 - mn0), sc1 = __expf(m1 - mn1);
        float s0 = 0.f, s1 = 0.f;
#pragma unroll
        for (int nf = 0; nf < 8; ++nf) {
            c[nf][0] = __expf(c[nf][0] - mn0); s0 += c[nf][0];
            c[nf][1] = __expf(c[nf][1] - mn0); s0 += c[nf][1];
            c[nf][2] = __expf(c[nf][2] - mn1); s1 += c[nf][2];
            c[nf][3] = __expf(c[nf][3] - mn1); s1 += c[nf][3];
        }
        s0 += __shfl_xor_sync(0xffffffffu, s0, 1);
        s0 += __shfl_xor_sync(0xffffffffu, s0, 2);
        s1 += __shfl_xor_sync(0xffffffffu, s1, 1);
        s1 += __shfl_xor_sync(0xffffffffu, s1, 2);
        l0 = l0 * sc0 + s0; l1 = l1 * sc1 + s1;
        m0 = mn0; m1 = mn1;
#pragma unroll
        for (int vf = 0; vf < 16; ++vf) {
            o[vf][0] *= sc0; o[vf][1] *= sc0;
            o[vf][2] *= sc1; o[vf][3] *= sc1;
        }

        // ---- O += P @ V ----
#pragma unroll
        for (int kt2 = 0; kt2 < 4; ++kt2) {
            uint32_t pa[4];
            pa[0] = packh2(c[2 * kt2][0],     c[2 * kt2][1]);
            pa[1] = packh2(c[2 * kt2][2],     c[2 * kt2][3]);
            pa[2] = packh2(c[2 * kt2 + 1][0], c[2 * kt2 + 1][1]);
            pa[3] = packh2(c[2 * kt2 + 1][2], c[2 * kt2 + 1][3]);
            const int kv0 = kt2 * 16 + tig * 2;
#pragma unroll
            for (int vf = 0; vf < 16; ++vf) {
                const int dv = vf * 8 + group;
                __half2 t0, t1;
                t0.x = Vs[kv0 * 136 + dv];
                t0.y = Vs[(kv0 + 1) * 136 + dv];
                t1.x = Vs[(kv0 + 8) * 136 + dv];
                t1.y = Vs[(kv0 + 9) * 136 + dv];
                uint32_t vb[2] = { *(uint32_t*)&t0, *(uint32_t*)&t1 };
                mma_f16(o[vf], pa, vb);
            }
        }
    }

    // ---- write out (fp32) ----
    const float inv0 = 1.f / l0, inv1 = 1.f / l1;
    const int grow0 = rowbase + qt * 128 + w * 16 + group;
#pragma unroll
    for (int vf = 0; vf < 16; ++vf) {
        const int col = h * 128 + vf * 8 + tig * 2;
        *(float2*)&Od[(size_t)grow0 * 2048 + col] =
            make_float2(o[vf][0] * inv0, o[vf][1] * inv0);
        *(float2*)&Od[(size_t)(grow0 + 8) * 2048 + col] =
            make_float2(o[vf][2] * inv1, o[vf][3] * inv1);
    }
}

// ---------------- per-segment memory outer product (half in, fp32 math) ----------------
__global__ __launch_bounds__(256) void pmat_k(
    const __half* __restrict__ Kg, const __half* __restrict__ Vg, float* __restrict__ P)
{
    __shared__ float sk[16][128];
    __shared__ float sv[16][128];
    const int tid = threadIdx.x;
    const int ty = tid >> 4, tx = tid & 15;
    const int seg = blockIdx.x, bh = blockIdx.y;
    const int b = bh >> 4, h = bh & 15;
    const int rowbase = b * 4096 + seg * 512;
    float acc[8][8] = {};

    for (int ck = 0; ck < 512; ck += 16) {
        __syncthreads();
        {
            const int r = tid >> 4;
            const int c8 = (tid & 15) << 3;
            size_t gi = (size_t)(rowbase + ck + r) * 6144 + h * 128 + c8;
            uint4 k4 = *(const uint4*)&Kg[gi];
            uint4 v4 = *(const uint4*)&Vg[gi];
            const __half* kh = (const __half*)&k4;
            const __half* vh = (const __half*)&v4;
#pragma unroll
            for (int i = 0; i < 8; ++i) {
                float xk = __half2float(kh[i]);
                sk[r][c8 + i] = xk > 0.f ? xk + 1.f : expf(xk);
                sv[r][c8 + i] = __half2float(vh[i]);
            }
        }
        __syncthreads();
#pragma unroll
        for (int s = 0; s < 16; ++s) {
            float av[8], bv[8];
            *(float4*)&av[0] = *(const float4*)&sk[s][ty * 8];
            *(float4*)&av[4] = *(const float4*)&sk[s][ty * 8 + 4];
            *(float4*)&bv[0] = *(const float4*)&sv[s][tx * 8];
            *(float4*)&bv[4] = *(const float4*)&sv[s][tx * 8 + 4];
#pragma unroll
            for (int i = 0; i < 8; ++i)
#pragma unroll
                for (int j = 0; j < 8; ++j)
                    acc[i][j] += av[i] * bv[j];
        }
    }

    float* Pp = P + ((size_t)bh * 8 + seg) * 16384;
#pragma unroll
    for (int i = 0; i < 8; ++i)
#pragma unroll
        for (int j = 0; j < 8; ++j)
            Pp[(ty * 8 + i) * 128 + tx * 8 + j] = acc[i][j];
}

// ---------------- z_i = sum elu(k)+1 ----------------
__global__ void zsum_k(const __half* __restrict__ Kg, float* __restrict__ z)
{
    int d = threadIdx.x;
    int seg = blockIdx.x, bh = blockIdx.y;
    int b = bh >> 4, h = bh & 15;
    const __half* Kp = Kg + (size_t)(b * 4096 + seg * 512) * 6144 + h * 128 + d;
    float s = 0.f;
    for (int i = 0; i < 512; ++i) {
        float x = __half2float(Kp[(size_t)i * 6144]);
        s += x > 0.f ? x + 1.f : expf(x);
    }
    z[((size_t)bh * 8 + seg) * 128 + d] = s;
}

// ---------------- exclusive prefix over segments ----------------
__global__ void prefix_k(const float* __restrict__ P, const float* __restrict__ z,
                         float* __restrict__ Mpre, float* __restrict__ zpre)
{
    int bh = blockIdx.x;
    int tid = threadIdx.x;
    for (int idx = tid; idx < 16384; idx += 256) {
        float run = 0.f;
        for (int s = 0; s < 8; ++s) {
            size_t o = ((size_t)bh * 8 + s) * 16384 + idx;
            Mpre[o] = run;
            run += P[o];
        }
    }
    if (tid < 128) {
        float run = 1.f / 128.f;
        for (int s = 0; s < 8; ++s) {
            size_t o = ((size_t)bh * 8 + s) * 128 + tid;
            zpre[o] = run;
            run += z[o];
        }
    }
}

// ---------------- att_mem + gated blend (half Q in, writes half) ----------------
__global__ __launch_bounds__(256) void combine_k(
    const __half* __restrict__ Q, const float* __restrict__ Mpre,
    const float* __restrict__ zpre, const float* __restrict__ attdot,
    const float* __restrict__ betas, __half* __restrict__ att)
{
    extern __shared__ float sm[];
    float* sqT = sm;
    float* Ms  = sqT + 128 * 64;
    float* zs  = Ms + 128 * 128;

    const int tid = threadIdx.x;
    const int ty = tid >> 4, tx = tid & 15;
    const int bh = blockIdx.z, b = bh >> 4, h = bh & 15;
    const int seg = blockIdx.y, qt = blockIdx.x;
    const int rowbase = b * 4096 + seg * 512;

#pragma unroll
    for (int u = 0; u < 4; ++u) {
        int fi = tid + u * 256;
        int r = fi >> 4;
        int c8 = (fi & 15) << 3;
        uint4 q4 = *(const uint4*)&Q[(size_t)(rowbase + qt * 64 + r) * 6144 + h * 128 + c8];
        const __half* qh = (const __half*)&q4;
#pragma unroll
        for (int i = 0; i < 8; ++i) {
            float x = __half2float(qh[i]);
            sqT[(c8 + i) * 64 + r] = x > 0.f ? x + 1.f : expf(x);
        }
    }
    {
        const float4* Mg = (const float4*)(Mpre + ((size_t)bh * 8 + seg) * 16384);
        float4* Ms4 = (float4*)Ms;
        for (int i = tid; i < 4096; i += 256) Ms4[i] = Mg[i];
        if (tid < 128) zs[tid] = zpre[((size_t)bh * 8 + seg) * 128 + tid];
    }
    __syncthreads();

    const int r0 = ty * 4, oc0 = tx * 8;
    float acc[4][8] = {};
    float den[4] = {};
#pragma unroll 4
    for (int k = 0; k < 128; ++k) {
        float4 a4 = *(const float4*)&sqT[k * 64 + r0];
        float av[4] = {a4.x, a4.y, a4.z, a4.w};
        float zk = zs[k];
        float4 b0 = *(const float4*)&Ms[k * 128 + oc0];
        float4 b1 = *(const float4*)&Ms[k * 128 + oc0 + 4];
        float bv[8] = {b0.x, b0.y, b0.z, b0.w, b1.x, b1.y, b1.z, b1.w};
#pragma unroll
        for (int i = 0; i < 4; ++i) {
            den[i] += av[i] * zk;
#pragma unroll
            for (int c = 0; c < 8; ++c)
                acc[i][c] += av[i] * bv[c];
        }
    }

#pragma unroll
    for (int i = 0; i < 4; ++i) {
        float inv = 1.f / den[i];
        size_t base = (size_t)(rowbase + qt * 64 + r0 + i) * 2048 + h * 128 + oc0;
#pragma unroll
        for (int c = 0; c < 8; c += 2) {
            float g0 = 1.f / (1.f + expf(-betas[h * 128 + oc0 + c]));
            float g1 = 1.f / (1.f + expf(-betas[h * 128 + oc0 + c + 1]));
            float o0 = g0 * (acc[i][c] * inv)     + (1.f - g0) * attdot[base + c];
            float o1 = g1 * (acc[i][c + 1] * inv) + (1.f - g1) * attdot[base + c + 1];
            *(__half2*)&att[base + c] = __floats2half2_rn(o0, o1);
        }
    }
}

// ---------------- residual + LayerNorm ----------------
__global__ __launch_bounds__(256) void ln_k(
    const float* __restrict__ y, const float* __restrict__ x,
    const float* __restrict__ gm, const float* __restrict__ bt,
    float* __restrict__ out)
{
    __shared__ float r1[8], r2[8];
    const int row = blockIdx.x, tid = threadIdx.x;
    const float* yp = y + (size_t)row * 2048;
    const float* xp = x + (size_t)row * 2048;
    float s1 = 0.f, s2 = 0.f;
    for (int c = tid; c < 2048; c += 256) {
        float v = yp[c] + xp[c];
        s1 += v; s2 += v * v;
    }
#pragma unroll
    for (int off = 16; off >= 1; off >>= 1) {
        s1 += __shfl_xor_sync(0xffffffffu, s1, off);
        s2 += __shfl_xor_sync(0xffffffffu, s2, off);
    }
    if ((tid & 31) == 0) { r1[tid >> 5] = s1; r2[tid >> 5] = s2; }
    __syncthreads();
    if (tid == 0) {
        float a = 0.f, bb = 0.f;
        for (int w = 0; w < 8; ++w) { a += r1[w]; bb += r2[w]; }
        r1[0] = a; r2[0] = bb;
    }
    __syncthreads();
    const float mu = r1[0] * (1.f / 2048.f);
    const float var = r2[0] * (1.f / 2048.f) - mu * mu;
    const float rs = rsqrtf(var + 1e-5f);
    for (int c = tid; c < 2048; c += 256) {
        float v = yp[c] + xp[c];
        out[(size_t)row * 2048 + c] = (v - mu) * rs * gm[c] + bt[c];
    }
}

// ---------------- host ----------------
extern "C" void kernel_launch(void* const* d_in, const int* in_sizes, int n_in,
                              void* d_out, int out_size)
{
    const float* x     = (const float*)d_in[0];
    const float* Wq    = (const float*)d_in[1];
    const float* Wk    = (const float*)d_in[2];
    const float* Wv    = (const float*)d_in[3];
    const float* Wo    = (const float*)d_in[4];
    const float* betas = (const float*)d_in[5];
    const float* W1    = (const float*)d_in[6];
    const float* b1    = (const float*)d_in[7];
    const float* W2    = (const float*)d_in[8];
    const float* b2    = (const float*)d_in[9];
    const float* lng   = (const float*)d_in[10];
    const float* lnb   = (const float*)d_in[11];
    float* out = (float*)d_out;

    float *AD, *Pb, *Mp, *zb, *zp, *YB;
    __half *QKV, *XH, *AT, *AO, *HB, *WqkvT, *WoT, *W1T, *W2T;
    cudaGetSymbolAddress((void**)&QKV, g_qkv);
    cudaGetSymbolAddress((void**)&XH, g_xh);
    cudaGetSymbolAddress((void**)&AD, g_attdot);
    cudaGetSymbolAddress((void**)&AT, g_att);
    cudaGetSymbolAddress((void**)&Pb, g_P);
    cudaGetSymbolAddress((void**)&Mp, g_Mpre);
    cudaGetSymbolAddress((void**)&zb, g_zz);
    cudaGetSymbolAddress((void**)&zp, g_zpre);
    cudaGetSymbolAddress((void**)&AO, g_ao);
    cudaGetSymbolAddress((void**)&HB, g_hb);
    cudaGetSymbolAddress((void**)&YB, g_yb);
    cudaGetSymbolAddress((void**)&WqkvT, g_WqkvT);
    cudaGetSymbolAddress((void**)&WoT, g_WoT);
    cudaGetSymbolAddress((void**)&W1T, g_W1T);
    cudaGetSymbolAddress((void**)&W2T, g_W2T);

    const __half* Kb = QKV + 2048;

    const int CMB_SMEM = (128 * 64 + 128 * 128 + 128) * 4;
    cudaFuncSetAttribute(attdot_mma, cudaFuncAttributeMaxDynamicSharedMemorySize, ATT2_SMEM);
    cudaFuncSetAttribute(combine_k, cudaFuncAttributeMaxDynamicSharedMemorySize, CMB_SMEM);
    cudaFuncSetAttribute((const void*)gemm_mma<false, false, __half>, cudaFuncAttributeMaxDynamicSharedMemorySize, GEMM_SMEM);
    cudaFuncSetAttribute((const void*)gemm_mma<true, true, __half>,   cudaFuncAttributeMaxDynamicSharedMemorySize, GEMM_SMEM);
    cudaFuncSetAttribute((const void*)gemm_mma<true, false, float>,   cudaFuncAttributeMaxDynamicSharedMemorySize, GEMM_SMEM);

    // ---- input convert + weight transposes ----
    cvt_h<<<8192, 256>>>(x, XH);
    transpose_h<<<dim3(64, 64), 256>>>(Wq, WqkvT, 2048, 2048);
    transpose_h<<<dim3(64, 64), 256>>>(Wk, WqkvT + 2048 * 2048, 2048, 2048);
    transpose_h<<<dim3(64, 64), 256>>>(Wv, WqkvT + 2 * 2048 * 2048, 2048, 2048);
    transpose_h<<<dim3(64, 64), 256>>>(Wo, WoT, 2048, 2048);
    transpose_h<<<dim3(256, 64), 256>>>(W1, W1T, 2048, 8192);
    transpose_h<<<dim3(64, 256), 256>>>(W2, W2T, 8192, 2048);

    // ---- fused QKV projection (half out) ----
    gemm_mma<false, false, __half><<<dim3(48, 64), 256, GEMM_SMEM>>>(XH, WqkvT, nullptr, QKV, 6144, 2048);

    // ---- attention ----
    attdot_mma<<<dim3(4, 8, 32), 256, ATT2_SMEM>>>(QKV, AD);
    dim3 gz(8, 32);
    zsum_k<<<gz, 128>>>(Kb, zb);
    pmat_k<<<gz, 256>>>(Kb, QKV + 4096, Pb);
    prefix_k<<<32, 256>>>(Pb, zb, Mp, zp);
    dim3 gc(8, 8, 32);
    combine_k<<<gc, 256, CMB_SMEM>>>(QKV, Mp, zp, AD, betas, AT);

    // ---- output projection + MLP ----
    gemm_mma<false, false, __half><<<dim3(16, 64), 256, GEMM_SMEM>>>(AT, WoT, nullptr, AO, 2048, 2048);
    gemm_mma<true, true, __half><<<dim3(64, 64), 256, GEMM_SMEM>>>(AO, W1T, b1, HB, 8192, 2048);
    gemm_mma<true, false, float><<<dim3(16, 64), 256, GEMM_SMEM>>>(HB, W2T, b2, YB, 2048, 8192);

    // ---- residual + LayerNorm ----
    ln_k<<<8192, 256>>>(YB, x, lng, lnb, out);
}